// round 6
// baseline (speedup 1.0000x reference)
#include <cuda_runtime.h>
#include <cfloat>
#include <cstdint>

#define Nn 100000
#define NnP 100096          // multiple of 128 (MMA tile) and 64
#define Ee 1600000
#define Dd 64
#define Gg 512
#define OUTD 16
#define NL 5
#define DELTA 2.5749f
#define BN_EPS 1e-5f

// ---------------- static device scratch ----------------
static __device__ float g_hA[NnP * Dd];
static __device__ float g_hB[NnP * Dd];
static __device__ float g_base[NnP * 256];     // [sum|max|mean|var]
static __device__ float g_cfac[NnP];
static __device__ int   g_deg[Nn];
static __device__ int   g_sc[Nn];
static __device__ int   g_bsum[128];
static __device__ int   g_rowptr[Nn + 1];
static __device__ int   g_cursor[Nn];
static __device__ int   g_esrc[Ee];
static __device__ float g_part[Gg * 2 * Dd];
static __device__ float g_scale[Dd];
static __device__ float g_shift[Dd];
static __device__ int   g_bstart[Gg + 1];
static __device__ float g_gpool[Gg * Dd];
static __device__ float g_encWt[Dd * Dd];
static __device__ float g_nnW1h[NL * Dd * Dd];  // [k][d] tf32 hi
static __device__ float g_nnW1l[NL * Dd * Dd];  // [k][d] tf32 lo
static __device__ float g_nnW2h[NL * Dd * Dd];
static __device__ float g_nnW2l[NL * Dd * Dd];
static __device__ float g_mlpBh[NL * 256 * 192];  // [k][n], tf32 hi
static __device__ float g_mlpBl[NL * 256 * 192];  // [k][n], tf32 lo residual
static __device__ float g_fc1Wt[Dd * Dd];
static __device__ float g_fc2Wt[Dd * OUTD];

__device__ __forceinline__ float tf32r(float x) {
    float y;
    asm("cvt.rna.tf32.f32 %0, %1;" : "=f"(y) : "f"(x));
    return y;
}
__device__ __forceinline__ void mma1688(float* c, const uint32_t* a, uint32_t b0, uint32_t b1) {
    asm volatile(
        "mma.sync.aligned.m16n8k8.row.col.f32.tf32.tf32.f32 "
        "{%0,%1,%2,%3}, {%4,%5,%6,%7}, {%8,%9}, {%0,%1,%2,%3};"
        : "+f"(c[0]), "+f"(c[1]), "+f"(c[2]), "+f"(c[3])
        : "r"(a[0]), "r"(a[1]), "r"(a[2]), "r"(a[3]), "r"(b0), "r"(b1));
}

// ---------------- CSR build ----------------
__global__ void k_zero_deg() {
    int i = blockIdx.x * blockDim.x + threadIdx.x;
    if (i < Nn) g_deg[i] = 0;
}
__global__ void k_count(const int* __restrict__ dst) {
    int e = blockIdx.x * blockDim.x + threadIdx.x;
    if (e < Ee) atomicAdd(&g_deg[dst[e]], 1);
}
__global__ void k_scan_block() {
    __shared__ int sm[1024];
    int i = blockIdx.x * 1024 + threadIdx.x;
    int v = (i < Nn) ? g_deg[i] : 0;
    sm[threadIdx.x] = v;
    __syncthreads();
    for (int off = 1; off < 1024; off <<= 1) {
        int t = 0;
        if (threadIdx.x >= off) t = sm[threadIdx.x - off];
        __syncthreads();
        sm[threadIdx.x] += t;
        __syncthreads();
    }
    if (i < Nn) g_sc[i] = sm[threadIdx.x];
    if (threadIdx.x == 1023) g_bsum[blockIdx.x] = sm[1023];
}
__global__ void k_scan_tops(int nb) {
    if (threadIdx.x == 0 && blockIdx.x == 0) {
        int run = 0;
        for (int b = 0; b < nb; b++) { int t = g_bsum[b]; g_bsum[b] = run; run += t; }
    }
}
__global__ void k_rowptr() {
    int i = blockIdx.x * blockDim.x + threadIdx.x;
    if (i < Nn) {
        int rp = g_sc[i] - g_deg[i] + g_bsum[i >> 10];
        g_rowptr[i] = rp;
        g_cursor[i] = rp;
        g_cfac[i] = fmaxf((float)g_deg[i], 1.0f);
    }
    if (i == 0) g_rowptr[Nn] = Ee;
}
__global__ void k_scatter(const int* __restrict__ src, const int* __restrict__ dst) {
    int e = blockIdx.x * blockDim.x + threadIdx.x;
    if (e < Ee) {
        int p = atomicAdd(&g_cursor[dst[e]], 1);
        g_esrc[p] = src[e];
    }
}
// deterministic within-row order; local-memory sort for typical degrees
__global__ void k_sortrows() {
    int n = blockIdx.x * blockDim.x + threadIdx.x;
    if (n >= Nn) return;
    int beg = g_rowptr[n], end = g_rowptr[n + 1];
    int deg = end - beg;
    if (deg <= 1) return;
    if (deg <= 128) {
        int buf[128];
        for (int i = 0; i < deg; i++) buf[i] = g_esrc[beg + i];
        for (int i = 1; i < deg; i++) {
            int v = buf[i];
            int j = i - 1;
            while (j >= 0 && buf[j] > v) { buf[j + 1] = buf[j]; j--; }
            buf[j + 1] = v;
        }
        for (int i = 0; i < deg; i++) g_esrc[beg + i] = buf[i];
    } else {
        for (int i = beg + 1; i < end; i++) {
            int v = g_esrc[i];
            int j = i - 1;
            while (j >= beg && g_esrc[j] > v) { g_esrc[j + 1] = g_esrc[j]; j--; }
            g_esrc[j + 1] = v;
        }
    }
}

// ---------------- weight prep ----------------
__global__ void k_t64(const float* __restrict__ W, float* __restrict__ Wt, int nm) {
    int idx = blockIdx.x * blockDim.x + threadIdx.x;
    if (idx >= nm * 4096) return;
    int m = idx >> 12, r = idx & 4095;
    int d = r >> 6, k = r & 63;
    Wt[(m << 12) + (k << 6) + d] = W[idx];
}
// [k][d] layout, hi/lo tf32 split
__global__ void k_t64split(const float* __restrict__ W, float* __restrict__ Wh,
                           float* __restrict__ Wl, int nm) {
    int idx = blockIdx.x * blockDim.x + threadIdx.x;
    if (idx >= nm * 4096) return;
    int m = idx >> 12, r = idx & 4095;
    int d = r >> 6, k = r & 63;
    float w = W[idx];
    float h = tf32r(w);
    Wh[(m << 12) + (k << 6) + d] = h;
    Wl[(m << 12) + (k << 6) + d] = tf32r(w - h);
}
// g_mlpB{h,l}[m][k*192+n] from mlpW[m][(n&63)*768 + (n>>6)*256 + k]
__global__ void k_tmlpB(const float* __restrict__ W) {
    int idx = blockIdx.x * blockDim.x + threadIdx.x;
    if (idx >= NL * 256 * 192) return;
    int m = idx / 49152, r = idx % 49152;
    int k = r / 192, n = r % 192;
    int d = n & 63, b = n >> 6;
    float w = W[m * 49152 + d * 768 + b * 256 + k];
    float h = tf32r(w);
    g_mlpBh[idx] = h;
    g_mlpBl[idx] = tf32r(w - h);
}
__global__ void k_tfc2(const float* __restrict__ W) {
    int idx = blockIdx.x * blockDim.x + threadIdx.x;
    if (idx >= Dd * OUTD) return;
    int o = idx >> 6, k = idx & 63;
    g_fc2Wt[k * 16 + o] = W[idx];
}

// ---------------- 64x64 linear (encoder only) ----------------
template <bool RELU>
__global__ void __launch_bounds__(64) k_lin64(const float* __restrict__ A,
                                              const float* __restrict__ Wt,
                                              const float* __restrict__ b,
                                              float* __restrict__ C) {
    __shared__ float4 Asm[64][16];
    int row0 = blockIdx.x * 64, tid = threadIdx.x;
    for (int t = tid; t < 1024; t += 64) {
        int r = t >> 4, c = t & 15;
        float4 v = make_float4(0.f, 0.f, 0.f, 0.f);
        if (row0 + r < Nn) v = ((const float4*)A)[(row0 + r) * 16 + c];
        Asm[r][c] = v;
    }
    __syncthreads();
    float acc[64];
#pragma unroll
    for (int r = 0; r < 64; r++) acc[r] = 0.f;
#pragma unroll 1
    for (int k4 = 0; k4 < 16; k4++) {
        float w0 = Wt[(k4 * 4 + 0) * 64 + tid];
        float w1 = Wt[(k4 * 4 + 1) * 64 + tid];
        float w2 = Wt[(k4 * 4 + 2) * 64 + tid];
        float w3 = Wt[(k4 * 4 + 3) * 64 + tid];
#pragma unroll
        for (int r = 0; r < 64; r++) {
            float4 a = Asm[r][k4];
            float t0 = fmaf(a.x, w0, acc[r]);
            t0 = fmaf(a.y, w1, t0);
            t0 = fmaf(a.z, w2, t0);
            acc[r] = fmaf(a.w, w3, t0);
        }
    }
    float bb = b[tid];
    for (int r = 0; r < 64; r++) {
        if (row0 + r < Nn) {
            float v = acc[r] + bb;
            if (RELU) v = fmaxf(v, 0.f);
            C[(row0 + r) * 64 + tid] = v;
        }
    }
}

// ---------------- PNA aggregation (warp/node, 2-way unrolled) ----------------
__global__ void k_agg() {
    int gt = blockIdx.x * blockDim.x + threadIdx.x;
    int w = gt >> 5, lane = gt & 31;
    if (w >= Nn) return;
    int beg = g_rowptr[w], end = g_rowptr[w + 1];
    const float2* hp = (const float2*)g_hA;
    float sxA = 0.f, syA = 0.f, qxA = 0.f, qyA = 0.f;
    float sxB = 0.f, syB = 0.f, qxB = 0.f, qyB = 0.f;
    float mxx = -FLT_MAX, mxy = -FLT_MAX;
    int j = beg;
    for (; j + 1 < end; j += 2) {
        int s0 = g_esrc[j];
        int s1 = g_esrc[j + 1];
        float2 v0 = hp[s0 * 32 + lane];
        float2 v1 = hp[s1 * 32 + lane];
        sxA += v0.x; syA += v0.y;
        qxA = fmaf(v0.x, v0.x, qxA);
        qyA = fmaf(v0.y, v0.y, qyA);
        mxx = fmaxf(mxx, v0.x);
        mxy = fmaxf(mxy, v0.y);
        sxB += v1.x; syB += v1.y;
        qxB = fmaf(v1.x, v1.x, qxB);
        qyB = fmaf(v1.y, v1.y, qyB);
        mxx = fmaxf(mxx, v1.x);
        mxy = fmaxf(mxy, v1.y);
    }
    if (j < end) {
        int s0 = g_esrc[j];
        float2 v0 = hp[s0 * 32 + lane];
        sxA += v0.x; syA += v0.y;
        qxA = fmaf(v0.x, v0.x, qxA);
        qyA = fmaf(v0.y, v0.y, qyA);
        mxx = fmaxf(mxx, v0.x);
        mxy = fmaxf(mxy, v0.y);
    }
    float sx = sxA + sxB, sy = syA + syB;
    float qx = qxA + qxB, qy = qyA + qyB;
    if (end == beg) { mxx = 0.f; mxy = 0.f; }
    float c = g_cfac[w];
    float inv = 1.f / c;
    float mex = sx * inv, mey = sy * inv;
    float vx = fmaxf(qx * inv - mex * mex, 0.f);
    float vy = fmaxf(qy * inv - mey * mey, 0.f);
    float2* bp = (float2*)(g_base + (size_t)w * 256);
    bp[lane]      = make_float2(sx, sy);
    bp[32 + lane] = make_float2(mxx, mxy);
    bp[64 + lane] = make_float2(mex, mey);
    bp[96 + lane] = make_float2(vx, vy);
}

// ---------------- 3xTF32 mma.sync GEMM + fused combine ----------------
#define AS_STRIDE 36
#define BS_STRIDE 200
#define SS_STRIDE 200
#define AH_OFFS 0
#define AL_OFFS (128 * AS_STRIDE)
#define BH_OFFS (2 * 128 * AS_STRIDE)
#define BL_OFFS (BH_OFFS + 32 * BS_STRIDE)
#define MMA_SMEM_FLOATS (128 * SS_STRIDE)
#define MMA_SMEM_BYTES (MMA_SMEM_FLOATS * 4)

__global__ void __launch_bounds__(384)
k_pna_mma(const float* __restrict__ Bh, const float* __restrict__ Bl,
          const float* __restrict__ mb) {
    extern __shared__ float sm[];
    float* Ash = sm + AH_OFFS;
    float* Asl = sm + AL_OFFS;
    float* Bsh = sm + BH_OFFS;
    float* Bsl = sm + BL_OFFS;
    int tid = threadIdx.x, wid = tid >> 5, lane = tid & 31;
    int gid = lane >> 2, tig = lane & 3;
    int row0 = blockIdx.x * 128;
    int mrow0 = (wid & 3) * 32;
    int ncol0 = (wid >> 2) * 64;

    float acc[2][8][4];
#pragma unroll
    for (int mt = 0; mt < 2; mt++)
#pragma unroll
        for (int nt = 0; nt < 8; nt++)
#pragma unroll
            for (int j = 0; j < 4; j++) acc[mt][nt][j] = 0.f;

#pragma unroll 1
    for (int kc = 0; kc < 8; kc++) {
        for (int i = tid; i < 1024; i += 384) {
            int r = i >> 3, c4 = i & 7;
            float4 v = *(const float4*)&g_base[(size_t)(row0 + r) * 256 + kc * 32 + c4 * 4];
            float4 h, l;
            h.x = tf32r(v.x); l.x = tf32r(v.x - h.x);
            h.y = tf32r(v.y); l.y = tf32r(v.y - h.y);
            h.z = tf32r(v.z); l.z = tf32r(v.z - h.z);
            h.w = tf32r(v.w); l.w = tf32r(v.w - h.w);
            *(float4*)&Ash[r * AS_STRIDE + c4 * 4] = h;
            *(float4*)&Asl[r * AS_STRIDE + c4 * 4] = l;
        }
        for (int i = tid; i < 1536; i += 384) {
            int r = i / 48, c4 = i % 48;
            size_t go = (size_t)(kc * 32 + r) * 192 + c4 * 4;
            *(float4*)&Bsh[r * BS_STRIDE + c4 * 4] = *(const float4*)&Bh[go];
            *(float4*)&Bsl[r * BS_STRIDE + c4 * 4] = *(const float4*)&Bl[go];
        }
        __syncthreads();
#pragma unroll
        for (int k8 = 0; k8 < 4; k8++) {
            int kb = k8 * 8;
            uint32_t ah[2][4], al[2][4];
#pragma unroll
            for (int mt = 0; mt < 2; mt++) {
                int mr = mrow0 + mt * 16 + gid;
                ah[mt][0] = __float_as_uint(Ash[mr * AS_STRIDE + kb + tig]);
                ah[mt][1] = __float_as_uint(Ash[(mr + 8) * AS_STRIDE + kb + tig]);
                ah[mt][2] = __float_as_uint(Ash[mr * AS_STRIDE + kb + tig + 4]);
                ah[mt][3] = __float_as_uint(Ash[(mr + 8) * AS_STRIDE + kb + tig + 4]);
                al[mt][0] = __float_as_uint(Asl[mr * AS_STRIDE + kb + tig]);
                al[mt][1] = __float_as_uint(Asl[(mr + 8) * AS_STRIDE + kb + tig]);
                al[mt][2] = __float_as_uint(Asl[mr * AS_STRIDE + kb + tig + 4]);
                al[mt][3] = __float_as_uint(Asl[(mr + 8) * AS_STRIDE + kb + tig + 4]);
            }
#pragma unroll
            for (int nt = 0; nt < 8; nt++) {
                int nc = ncol0 + nt * 8 + gid;
                uint32_t bh0 = __float_as_uint(Bsh[(kb + tig) * BS_STRIDE + nc]);
                uint32_t bh1 = __float_as_uint(Bsh[(kb + tig + 4) * BS_STRIDE + nc]);
                uint32_t bl0 = __float_as_uint(Bsl[(kb + tig) * BS_STRIDE + nc]);
                uint32_t bl1 = __float_as_uint(Bsl[(kb + tig + 4) * BS_STRIDE + nc]);
                mma1688(acc[0][nt], ah[0], bh0, bh1);
                mma1688(acc[0][nt], ah[0], bl0, bl1);
                mma1688(acc[0][nt], al[0], bh0, bh1);
                mma1688(acc[1][nt], ah[1], bh0, bh1);
                mma1688(acc[1][nt], ah[1], bl0, bl1);
                mma1688(acc[1][nt], al[1], bh0, bh1);
            }
        }
        __syncthreads();
    }

#pragma unroll
    for (int mt = 0; mt < 2; mt++) {
#pragma unroll
        for (int nt = 0; nt < 8; nt++) {
            int r = mrow0 + mt * 16 + gid;
            int c = ncol0 + nt * 8 + tig * 2;
            *(float2*)&sm[r * SS_STRIDE + c] = make_float2(acc[mt][nt][0], acc[mt][nt][1]);
            *(float2*)&sm[(r + 8) * SS_STRIDE + c] = make_float2(acc[mt][nt][2], acc[mt][nt][3]);
        }
    }
    __syncthreads();

    for (int i = tid; i < 128 * 64; i += 384) {
        int r = i >> 6, d = i & 63;
        int row = row0 + r;
        if (row < Nn) {
            float cf = g_cfac[row];
            float aa = cf * (1.0f / DELTA);
            float b2 = DELTA / cf;
            const float* Sr = sm + r * SS_STRIDE;
            float v = g_hA[(size_t)row * 64 + d] + mb[d]
                    + Sr[d] + aa * Sr[64 + d] + b2 * Sr[128 + d];
            g_hB[(size_t)row * 64 + d] = v;
        }
    }
}

// ---------------- fused nn: hB = relu(relu(hB@W1t+b1)@W2t+b2), 3xTF32 ----------------
// CTA 128 rows, 256 threads = 8 warps (4m x 2n), warp tile 32x32.
#define FA_STRIDE 68
#define FW_STRIDE 72
#define F_ASH 0
#define F_ASL (128 * FA_STRIDE)              // 8704
#define F_W1H (2 * 128 * FA_STRIDE)          // 17408
#define F_W1L (F_W1H + 64 * FW_STRIDE)
#define F_W2H (F_W1L + 64 * FW_STRIDE)
#define F_W2L (F_W2H + 64 * FW_STRIDE)
#define F_SMEM_FLOATS (F_W2L + 64 * FW_STRIDE)   // 35840
#define F_SMEM_BYTES (F_SMEM_FLOATS * 4)         // 143360

__global__ void __launch_bounds__(256)
k_nn_mma(const float* __restrict__ W1h, const float* __restrict__ W1l,
         const float* __restrict__ W2h, const float* __restrict__ W2l,
         const float* __restrict__ b1, const float* __restrict__ b2) {
    extern __shared__ float sm[];
    float* Ash = sm + F_ASH;
    float* Asl = sm + F_ASL;
    float* w1h = sm + F_W1H;
    float* w1l = sm + F_W1L;
    float* w2h = sm + F_W2H;
    float* w2l = sm + F_W2L;
    int tid = threadIdx.x, wid = tid >> 5, lane = tid & 31;
    int gid = lane >> 2, tig = lane & 3;
    int row0 = blockIdx.x * 128;
    int mrow0 = (wid & 3) * 32;
    int ncol0 = (wid >> 2) * 32;

    // load weights into smem (stride 72 -> bank offset 8/row)
    for (int i = tid; i < 4096; i += 256) {
        int k = i >> 6, d = i & 63;
        int so = k * FW_STRIDE + d;
        w1h[so] = W1h[i];
        w1l[so] = W1l[i];
        w2h[so] = W2h[i];
        w2l[so] = W2l[i];
    }
    // load A = g_hB tile, split hi/lo
    for (int i = tid; i < 2048; i += 256) {
        int r = i >> 4, c4 = i & 15;
        float4 v = *(const float4*)&g_hB[(size_t)(row0 + r) * 64 + c4 * 4];
        float4 h, l;
        h.x = tf32r(v.x); l.x = tf32r(v.x - h.x);
        h.y = tf32r(v.y); l.y = tf32r(v.y - h.y);
        h.z = tf32r(v.z); l.z = tf32r(v.z - h.z);
        h.w = tf32r(v.w); l.w = tf32r(v.w - h.w);
        *(float4*)&Ash[r * FA_STRIDE + c4 * 4] = h;
        *(float4*)&Asl[r * FA_STRIDE + c4 * 4] = l;
    }
    __syncthreads();

    float acc[2][4][4];

    // ---- stage 1: t = relu(A @ W1t + b1) ----
#pragma unroll
    for (int mt = 0; mt < 2; mt++)
#pragma unroll
        for (int nt = 0; nt < 4; nt++)
#pragma unroll
            for (int j = 0; j < 4; j++) acc[mt][nt][j] = 0.f;

#pragma unroll 1
    for (int k8 = 0; k8 < 8; k8++) {
        int kb = k8 * 8;
        uint32_t ah[2][4], al[2][4];
#pragma unroll
        for (int mt = 0; mt < 2; mt++) {
            int mr = mrow0 + mt * 16 + gid;
            ah[mt][0] = __float_as_uint(Ash[mr * FA_STRIDE + kb + tig]);
            ah[mt][1] = __float_as_uint(Ash[(mr + 8) * FA_STRIDE + kb + tig]);
            ah[mt][2] = __float_as_uint(Ash[mr * FA_STRIDE + kb + tig + 4]);
            ah[mt][3] = __float_as_uint(Ash[(mr + 8) * FA_STRIDE + kb + tig + 4]);
            al[mt][0] = __float_as_uint(Asl[mr * FA_STRIDE + kb + tig]);
            al[mt][1] = __float_as_uint(Asl[(mr + 8) * FA_STRIDE + kb + tig]);
            al[mt][2] = __float_as_uint(Asl[mr * FA_STRIDE + kb + tig + 4]);
            al[mt][3] = __float_as_uint(Asl[(mr + 8) * FA_STRIDE + kb + tig + 4]);
        }
#pragma unroll
        for (int nt = 0; nt < 4; nt++) {
            int nc = ncol0 + nt * 8 + gid;
            uint32_t bh0 = __float_as_uint(w1h[(kb + tig) * FW_STRIDE + nc]);
            uint32_t bh1 = __float_as_uint(w1h[(kb + tig + 4) * FW_STRIDE + nc]);
            uint32_t bl0 = __float_as_uint(w1l[(kb + tig) * FW_STRIDE + nc]);
            uint32_t bl1 = __float_as_uint(w1l[(kb + tig + 4) * FW_STRIDE + nc]);
            mma1688(acc[0][nt], ah[0], bh0, bh1);
            mma1688(acc[0][nt], ah[0], bl0, bl1);
            mma1688(acc[0][nt], al[0], bh0, bh1);
            mma1688(acc[1][nt], ah[1], bh0, bh1);
            mma1688(acc[1][nt], ah[1], bl0, bl1);
            mma1688(acc[1][nt], al[1], bh0, bh1);
        }
    }
    __syncthreads();   // everyone done reading Ash/Asl

    // relu + bias, re-split into Ash/Asl
#pragma unroll
    for (int mt = 0; mt < 2; mt++) {
#pragma unroll
        for (int nt = 0; nt < 4; nt++) {
            int r = mrow0 + mt * 16 + gid;
            int c = ncol0 + nt * 8 + tig * 2;
            float bb0 = b1[c], bb1 = b1[c + 1];
            float u0 = fmaxf(acc[mt][nt][0] + bb0, 0.f);
            float u1 = fmaxf(acc[mt][nt][1] + bb1, 0.f);
            float u2 = fmaxf(acc[mt][nt][2] + bb0, 0.f);
            float u3 = fmaxf(acc[mt][nt][3] + bb1, 0.f);
            float h0 = tf32r(u0), h1 = tf32r(u1), h2 = tf32r(u2), h3 = tf32r(u3);
            Ash[r * FA_STRIDE + c] = h0;
            Ash[r * FA_STRIDE + c + 1] = h1;
            Ash[(r + 8) * FA_STRIDE + c] = h2;
            Ash[(r + 8) * FA_STRIDE + c + 1] = h3;
            Asl[r * FA_STRIDE + c] = tf32r(u0 - h0);
            Asl[r * FA_STRIDE + c + 1] = tf32r(u1 - h1);
            Asl[(r + 8) * FA_STRIDE + c] = tf32r(u2 - h2);
            Asl[(r + 8) * FA_STRIDE + c + 1] = tf32r(u3 - h3);
        }
    }
    __syncthreads();

    // ---- stage 2: hB = relu(t @ W2t + b2) ----
#pragma unroll
    for (int mt = 0; mt < 2; mt++)
#pragma unroll
        for (int nt = 0; nt < 4; nt++)
#pragma unroll
            for (int j = 0; j < 4; j++) acc[mt][nt][j] = 0.f;

#pragma unroll 1
    for (int k8 = 0; k8 < 8; k8++) {
        int kb = k8 * 8;
        uint32_t ah[2][4], al[2][4];
#pragma unroll
        for (int mt = 0; mt < 2; mt++) {
            int mr = mrow0 + mt * 16 + gid;
            ah[mt][0] = __float_as_uint(Ash[mr * FA_STRIDE + kb + tig]);
            ah[mt][1] = __float_as_uint(Ash[(mr + 8) * FA_STRIDE + kb + tig]);
            ah[mt][2] = __float_as_uint(Ash[mr * FA_STRIDE + kb + tig + 4]);
            ah[mt][3] = __float_as_uint(Ash[(mr + 8) * FA_STRIDE + kb + tig + 4]);
            al[mt][0] = __float_as_uint(Asl[mr * FA_STRIDE + kb + tig]);
            al[mt][1] = __float_as_uint(Asl[(mr + 8) * FA_STRIDE + kb + tig]);
            al[mt][2] = __float_as_uint(Asl[mr * FA_STRIDE + kb + tig + 4]);
            al[mt][3] = __float_as_uint(Asl[(mr + 8) * FA_STRIDE + kb + tig + 4]);
        }
#pragma unroll
        for (int nt = 0; nt < 4; nt++) {
            int nc = ncol0 + nt * 8 + gid;
            uint32_t bh0 = __float_as_uint(w2h[(kb + tig) * FW_STRIDE + nc]);
            uint32_t bh1 = __float_as_uint(w2h[(kb + tig + 4) * FW_STRIDE + nc]);
            uint32_t bl0 = __float_as_uint(w2l[(kb + tig) * FW_STRIDE + nc]);
            uint32_t bl1 = __float_as_uint(w2l[(kb + tig + 4) * FW_STRIDE + nc]);
            mma1688(acc[0][nt], ah[0], bh0, bh1);
            mma1688(acc[0][nt], ah[0], bl0, bl1);
            mma1688(acc[0][nt], al[0], bh0, bh1);
            mma1688(acc[1][nt], ah[1], bh0, bh1);
            mma1688(acc[1][nt], ah[1], bl0, bl1);
            mma1688(acc[1][nt], al[1], bh0, bh1);
        }
    }

    // epilogue: outer relu, write back to g_hB
#pragma unroll
    for (int mt = 0; mt < 2; mt++) {
#pragma unroll
        for (int nt = 0; nt < 4; nt++) {
            int r = mrow0 + mt * 16 + gid;
            int c = ncol0 + nt * 8 + tig * 2;
            float bb0 = b2[c], bb1 = b2[c + 1];
            int row = row0 + r;
            if (row < Nn) {
                float v0 = fmaxf(acc[mt][nt][0] + bb0, 0.f);
                float v1 = fmaxf(acc[mt][nt][1] + bb1, 0.f);
                *(float2*)&g_hB[(size_t)row * 64 + c] = make_float2(v0, v1);
            }
            if (row + 8 < Nn) {
                float v2 = fmaxf(acc[mt][nt][2] + bb0, 0.f);
                float v3 = fmaxf(acc[mt][nt][3] + bb1, 0.f);
                *(float2*)&g_hB[(size_t)(row + 8) * 64 + c] = make_float2(v2, v3);
            }
        }
    }
}

// ---------------- batchnorm ----------------
#define BN_CHUNK ((Nn + Gg - 1) / Gg)
__global__ void k_bnpart() {
    int b = blockIdx.x, d = threadIdx.x;
    int r0 = b * BN_CHUNK;
    int r1 = min(r0 + BN_CHUNK, Nn);
    float s = 0.f, q = 0.f;
    for (int r = r0; r < r1; r++) {
        float v = g_hB[r * 64 + d];
        s += v;
        q = fmaf(v, v, q);
    }
    g_part[b * 128 + d] = s;
    g_part[b * 128 + 64 + d] = q;
}
__global__ void k_bnfin(const float* __restrict__ gamma, const float* __restrict__ beta) {
    int d = threadIdx.x;
    float s = 0.f, q = 0.f;
    for (int b = 0; b < Gg; b++) {
        s += g_part[b * 128 + d];
        q += g_part[b * 128 + 64 + d];
    }
    float mean = s * (1.0f / Nn);
    float var = q * (1.0f / Nn) - mean * mean;
    float sc = gamma[d] * rsqrtf(var + BN_EPS);
    g_scale[d] = sc;
    g_shift[d] = fmaf(-mean, sc, beta[d]);
}
__global__ void k_bnapply() {
    int idx = blockIdx.x * blockDim.x + threadIdx.x;
    if (idx >= Nn * Dd) return;
    int d = idx & 63;
    g_hA[idx] = fmaf(g_hB[idx], g_scale[d], g_shift[d]);
}

// ---------------- pooling + head ----------------
__global__ void k_bounds(const int* __restrict__ batch) {
    int g = blockIdx.x * blockDim.x + threadIdx.x;
    if (g > Gg) return;
    if (g == Gg) { g_bstart[Gg] = Nn; return; }
    int lo = 0, hi = Nn;
    while (lo < hi) {
        int mid = (lo + hi) >> 1;
        if (batch[mid] < g) lo = mid + 1; else hi = mid;
    }
    g_bstart[g] = lo;
}
__global__ void k_pool() {
    int g = blockIdx.x, d = threadIdx.x;
    int r0 = g_bstart[g], r1 = g_bstart[g + 1];
    float s = 0.f;
    for (int r = r0; r < r1; r++) s += g_hA[r * 64 + d];
    g_gpool[g * 64 + d] = s;
}
__global__ void k_head(const float* __restrict__ fc1b, const float* __restrict__ fc2b,
                       float* __restrict__ out) {
    __shared__ float gsm[64], tsm[64];
    int g = blockIdx.x, d = threadIdx.x;
    gsm[d] = g_gpool[g * 64 + d];
    __syncthreads();
    float acc = fc1b[d];
    for (int k = 0; k < 64; k++) acc = fmaf(gsm[k], g_fc1Wt[k * 64 + d], acc);
    tsm[d] = fmaxf(acc, 0.f);
    __syncthreads();
    if (d < OUTD) {
        float a2 = fc2b[d];
        for (int k = 0; k < 64; k++) a2 = fmaf(tsm[k], g_fc2Wt[k * 16 + d], a2);
        out[g * OUTD + d] = a2;
    }
}

// ---------------- host ----------------
extern "C" void kernel_launch(void* const* d_in, const int* in_sizes, int n_in,
                              void* d_out, int out_size) {
    const float* x    = (const float*)d_in[0];
    const int*   ei   = (const int*)d_in[1];
    const int*   src  = ei;
    const int*   dst  = ei + Ee;
    const int*   batch = (const int*)d_in[2];
    const float* encW = (const float*)d_in[3];
    const float* encb = (const float*)d_in[4];
    const float* nnW1 = (const float*)d_in[5];
    const float* nnb1 = (const float*)d_in[6];
    const float* nnW2 = (const float*)d_in[7];
    const float* nnb2 = (const float*)d_in[8];
    const float* mlpW = (const float*)d_in[9];
    const float* mlpb = (const float*)d_in[10];
    const float* bnG  = (const float*)d_in[11];
    const float* bnB  = (const float*)d_in[12];
    const float* fc1W = (const float*)d_in[13];
    const float* fc1b = (const float*)d_in[14];
    const float* fc2W = (const float*)d_in[15];
    const float* fc2b = (const float*)d_in[16];
    float* out = (float*)d_out;

    float *p_hA, *p_encWt, *p_fc1Wt, *p_mlpBh, *p_mlpBl;
    float *p_W1h, *p_W1l, *p_W2h, *p_W2l;
    cudaGetSymbolAddress((void**)&p_hA, g_hA);
    cudaGetSymbolAddress((void**)&p_encWt, g_encWt);
    cudaGetSymbolAddress((void**)&p_fc1Wt, g_fc1Wt);
    cudaGetSymbolAddress((void**)&p_mlpBh, g_mlpBh);
    cudaGetSymbolAddress((void**)&p_mlpBl, g_mlpBl);
    cudaGetSymbolAddress((void**)&p_W1h, g_nnW1h);
    cudaGetSymbolAddress((void**)&p_W1l, g_nnW1l);
    cudaGetSymbolAddress((void**)&p_W2h, g_nnW2h);
    cudaGetSymbolAddress((void**)&p_W2l, g_nnW2l);

    cudaFuncSetAttribute(k_pna_mma, cudaFuncAttributeMaxDynamicSharedMemorySize, MMA_SMEM_BYTES);
    cudaFuncSetAttribute(k_nn_mma, cudaFuncAttributeMaxDynamicSharedMemorySize, F_SMEM_BYTES);

    const int NB_SCAN = (Nn + 1023) / 1024;

    // CSR build
    k_zero_deg<<<(Nn + 255) / 256, 256>>>();
    k_count<<<(Ee + 255) / 256, 256>>>(dst);
    k_scan_block<<<NB_SCAN, 1024>>>();
    k_scan_tops<<<1, 1>>>(NB_SCAN);
    k_rowptr<<<(Nn + 255) / 256, 256>>>();
    k_scatter<<<(Ee + 255) / 256, 256>>>(src, dst);
    k_sortrows<<<(Nn + 255) / 256, 256>>>();

    // weight prep
    k_t64<<<(4096 + 255) / 256, 256>>>(encW, p_encWt, 1);
    k_t64<<<(4096 + 255) / 256, 256>>>(fc1W, p_fc1Wt, 1);
    k_t64split<<<(5 * 4096 + 255) / 256, 256>>>(nnW1, p_W1h, p_W1l, 5);
    k_t64split<<<(5 * 4096 + 255) / 256, 256>>>(nnW2, p_W2h, p_W2l, 5);
    k_tmlpB<<<(NL * 256 * 192 + 255) / 256, 256>>>(mlpW);
    k_tfc2<<<(Dd * OUTD + 255) / 256, 256>>>(fc2W);

    const int NBLIN = NnP / 64;    // 1564
    const int NBMMA = NnP / 128;   // 782

    k_lin64<false><<<NBLIN, 64>>>(x, p_encWt, encb, p_hA);

    for (int i = 0; i < NL; i++) {
        k_agg<<<(Nn * 32 + 255) / 256, 256>>>();
        k_pna_mma<<<NBMMA, 384, MMA_SMEM_BYTES>>>(p_mlpBh + i * 49152, p_mlpBl + i * 49152, mlpb + i * Dd);
        k_nn_mma<<<NBMMA, 256, F_SMEM_BYTES>>>(p_W1h + i * 4096, p_W1l + i * 4096,
                                               p_W2h + i * 4096, p_W2l + i * 4096,
                                               nnb1 + i * Dd, nnb2 + i * Dd);
        k_bnpart<<<Gg, 64>>>();
        k_bnfin<<<1, 64>>>(bnG + i * Dd, bnB + i * Dd);
        k_bnapply<<<(Nn * Dd + 255) / 256, 256>>>();
    }

    k_bounds<<<(Gg + 1 + 255) / 256, 256>>>(batch);
    k_pool<<<Gg, 64>>>();
    k_head<<<Gg, 64>>>(fc1b, fc2b, out);
}

// round 7
// speedup vs baseline: 1.0302x; 1.0302x over previous
#include <cuda_runtime.h>
#include <cfloat>
#include <cstdint>

#define Nn 100000
#define NnP 100096          // multiple of 128 (MMA tile)
#define Ee 1600000
#define Dd 64
#define Gg 512
#define OUTD 16
#define NL 5
#define DELTA 2.5749f
#define BN_EPS 1e-5f
#define NBMMA (NnP / 128)   // 782

// ---------------- static device scratch ----------------
static __device__ float g_hB[NnP * Dd];        // layer output (pre-BN)
static __device__ float g_hC[NnP * Dd];        // combine intermediate
static __device__ float g_base[NnP * 256];     // [sum|max|mean|var]
static __device__ float g_cfac[NnP];
static __device__ int   g_deg[Nn];
static __device__ int   g_sc[Nn];
static __device__ int   g_bsum[128];
static __device__ int   g_rowptr[Nn + 1];
static __device__ int   g_cursor[Nn];
static __device__ int   g_esrc[Ee];
static __device__ float g_part[NBMMA * 128];   // per-CTA BN partials
static __device__ float g_scale[Dd];
static __device__ float g_shift[Dd];
static __device__ int   g_bstart[Gg + 1];
static __device__ float g_gpool[Gg * Dd];
static __device__ float g_encWt[Dd * Dd];
static __device__ float g_nnW1h[NL * Dd * Dd];  // [k][d] tf32 hi
static __device__ float g_nnW1l[NL * Dd * Dd];  // [k][d] tf32 lo
static __device__ float g_nnW2h[NL * Dd * Dd];
static __device__ float g_nnW2l[NL * Dd * Dd];
static __device__ float g_mlpBh[NL * 256 * 192];  // [k][n], tf32 hi
static __device__ float g_mlpBl[NL * 256 * 192];  // [k][n], tf32 lo residual
static __device__ float g_fc1Wt[Dd * Dd];
static __device__ float g_fc2Wt[Dd * OUTD];

__device__ __forceinline__ float tf32r(float x) {
    float y;
    asm("cvt.rna.tf32.f32 %0, %1;" : "=f"(y) : "f"(x));
    return y;
}
__device__ __forceinline__ void mma1688(float* c, const uint32_t* a, uint32_t b0, uint32_t b1) {
    asm volatile(
        "mma.sync.aligned.m16n8k8.row.col.f32.tf32.tf32.f32 "
        "{%0,%1,%2,%3}, {%4,%5,%6,%7}, {%8,%9}, {%0,%1,%2,%3};"
        : "+f"(c[0]), "+f"(c[1]), "+f"(c[2]), "+f"(c[3])
        : "r"(a[0]), "r"(a[1]), "r"(a[2]), "r"(a[3]), "r"(b0), "r"(b1));
}

// ---------------- CSR build ----------------
__global__ void k_zero_deg() {
    int i = blockIdx.x * blockDim.x + threadIdx.x;
    if (i < Nn) g_deg[i] = 0;
}
__global__ void k_count(const int* __restrict__ dst) {
    int e = blockIdx.x * blockDim.x + threadIdx.x;
    if (e < Ee) atomicAdd(&g_deg[dst[e]], 1);
}
__global__ void k_scan_block() {
    __shared__ int sm[1024];
    int i = blockIdx.x * 1024 + threadIdx.x;
    int v = (i < Nn) ? g_deg[i] : 0;
    sm[threadIdx.x] = v;
    __syncthreads();
    for (int off = 1; off < 1024; off <<= 1) {
        int t = 0;
        if (threadIdx.x >= off) t = sm[threadIdx.x - off];
        __syncthreads();
        sm[threadIdx.x] += t;
        __syncthreads();
    }
    if (i < Nn) g_sc[i] = sm[threadIdx.x];
    if (threadIdx.x == 1023) g_bsum[blockIdx.x] = sm[1023];
}
__global__ void k_scan_tops(int nb) {
    if (threadIdx.x == 0 && blockIdx.x == 0) {
        int run = 0;
        for (int b = 0; b < nb; b++) { int t = g_bsum[b]; g_bsum[b] = run; run += t; }
    }
}
__global__ void k_rowptr() {
    int i = blockIdx.x * blockDim.x + threadIdx.x;
    if (i < Nn) {
        int rp = g_sc[i] - g_deg[i] + g_bsum[i >> 10];
        g_rowptr[i] = rp;
        g_cursor[i] = rp;
        g_cfac[i] = fmaxf((float)g_deg[i], 1.0f);
    }
    if (i == 0) g_rowptr[Nn] = Ee;
}
__global__ void k_scatter(const int* __restrict__ src, const int* __restrict__ dst) {
    int e = blockIdx.x * blockDim.x + threadIdx.x;
    if (e < Ee) {
        int p = atomicAdd(&g_cursor[dst[e]], 1);
        g_esrc[p] = src[e];
    }
}
__global__ void k_sortrows() {
    int n = blockIdx.x * blockDim.x + threadIdx.x;
    if (n >= Nn) return;
    int beg = g_rowptr[n], end = g_rowptr[n + 1];
    int deg = end - beg;
    if (deg <= 1) return;
    if (deg <= 128) {
        int buf[128];
        for (int i = 0; i < deg; i++) buf[i] = g_esrc[beg + i];
        for (int i = 1; i < deg; i++) {
            int v = buf[i];
            int j = i - 1;
            while (j >= 0 && buf[j] > v) { buf[j + 1] = buf[j]; j--; }
            buf[j + 1] = v;
        }
        for (int i = 0; i < deg; i++) g_esrc[beg + i] = buf[i];
    } else {
        for (int i = beg + 1; i < end; i++) {
            int v = g_esrc[i];
            int j = i - 1;
            while (j >= beg && g_esrc[j] > v) { g_esrc[j + 1] = g_esrc[j]; j--; }
            g_esrc[j + 1] = v;
        }
    }
}

// ---------------- weight prep ----------------
__global__ void k_t64(const float* __restrict__ W, float* __restrict__ Wt, int nm) {
    int idx = blockIdx.x * blockDim.x + threadIdx.x;
    if (idx >= nm * 4096) return;
    int m = idx >> 12, r = idx & 4095;
    int d = r >> 6, k = r & 63;
    Wt[(m << 12) + (k << 6) + d] = W[idx];
}
__global__ void k_t64split(const float* __restrict__ W, float* __restrict__ Wh,
                           float* __restrict__ Wl, int nm) {
    int idx = blockIdx.x * blockDim.x + threadIdx.x;
    if (idx >= nm * 4096) return;
    int m = idx >> 12, r = idx & 4095;
    int d = r >> 6, k = r & 63;
    float w = W[idx];
    float h = tf32r(w);
    Wh[(m << 12) + (k << 6) + d] = h;
    Wl[(m << 12) + (k << 6) + d] = tf32r(w - h);
}
__global__ void k_tmlpB(const float* __restrict__ W) {
    int idx = blockIdx.x * blockDim.x + threadIdx.x;
    if (idx >= NL * 256 * 192) return;
    int m = idx / 49152, r = idx % 49152;
    int k = r / 192, n = r % 192;
    int d = n & 63, b = n >> 6;
    float w = W[m * 49152 + d * 768 + b * 256 + k];
    float h = tf32r(w);
    g_mlpBh[idx] = h;
    g_mlpBl[idx] = tf32r(w - h);
}
// also initializes identity affine for layer 0
__global__ void k_tfc2(const float* __restrict__ W) {
    int idx = blockIdx.x * blockDim.x + threadIdx.x;
    if (idx < 64) { g_scale[idx] = 1.0f; g_shift[idx] = 0.0f; }
    if (idx >= Dd * OUTD) return;
    int o = idx >> 6, k = idx & 63;
    g_fc2Wt[k * 16 + o] = W[idx];
}

// ---------------- 64x64 linear (encoder only) ----------------
template <bool RELU>
__global__ void __launch_bounds__(64) k_lin64(const float* __restrict__ A,
                                              const float* __restrict__ Wt,
                                              const float* __restrict__ b,
                                              float* __restrict__ C) {
    __shared__ float4 Asm[64][16];
    int row0 = blockIdx.x * 64, tid = threadIdx.x;
    for (int t = tid; t < 1024; t += 64) {
        int r = t >> 4, c = t & 15;
        float4 v = make_float4(0.f, 0.f, 0.f, 0.f);
        if (row0 + r < Nn) v = ((const float4*)A)[(row0 + r) * 16 + c];
        Asm[r][c] = v;
    }
    __syncthreads();
    float acc[64];
#pragma unroll
    for (int r = 0; r < 64; r++) acc[r] = 0.f;
#pragma unroll 1
    for (int k4 = 0; k4 < 16; k4++) {
        float w0 = Wt[(k4 * 4 + 0) * 64 + tid];
        float w1 = Wt[(k4 * 4 + 1) * 64 + tid];
        float w2 = Wt[(k4 * 4 + 2) * 64 + tid];
        float w3 = Wt[(k4 * 4 + 3) * 64 + tid];
#pragma unroll
        for (int r = 0; r < 64; r++) {
            float4 a = Asm[r][k4];
            float t0 = fmaf(a.x, w0, acc[r]);
            t0 = fmaf(a.y, w1, t0);
            t0 = fmaf(a.z, w2, t0);
            acc[r] = fmaf(a.w, w3, t0);
        }
    }
    float bb = b[tid];
    for (int r = 0; r < 64; r++) {
        if (row0 + r < Nn) {
            float v = acc[r] + bb;
            if (RELU) v = fmaxf(v, 0.f);
            C[(row0 + r) * 64 + tid] = v;
        }
    }
}

// ---------------- PNA aggregation (warp/node, BN-affine on the fly) ----------------
__global__ void k_agg() {
    int gt = blockIdx.x * blockDim.x + threadIdx.x;
    int w = gt >> 5, lane = gt & 31;
    if (w >= Nn) return;
    int beg = g_rowptr[w], end = g_rowptr[w + 1];
    const float2* hp = (const float2*)g_hB;
    float scx = g_scale[2 * lane], scy = g_scale[2 * lane + 1];
    float shx = g_shift[2 * lane], shy = g_shift[2 * lane + 1];
    float sxA = 0.f, syA = 0.f, qxA = 0.f, qyA = 0.f;
    float sxB = 0.f, syB = 0.f, qxB = 0.f, qyB = 0.f;
    float mxx = -FLT_MAX, mxy = -FLT_MAX;
    int j = beg;
    for (; j + 1 < end; j += 2) {
        int s0 = g_esrc[j];
        int s1 = g_esrc[j + 1];
        float2 r0 = hp[s0 * 32 + lane];
        float2 r1 = hp[s1 * 32 + lane];
        float v0x = fmaf(r0.x, scx, shx), v0y = fmaf(r0.y, scy, shy);
        float v1x = fmaf(r1.x, scx, shx), v1y = fmaf(r1.y, scy, shy);
        sxA += v0x; syA += v0y;
        qxA = fmaf(v0x, v0x, qxA);
        qyA = fmaf(v0y, v0y, qyA);
        mxx = fmaxf(mxx, v0x);
        mxy = fmaxf(mxy, v0y);
        sxB += v1x; syB += v1y;
        qxB = fmaf(v1x, v1x, qxB);
        qyB = fmaf(v1y, v1y, qyB);
        mxx = fmaxf(mxx, v1x);
        mxy = fmaxf(mxy, v1y);
    }
    if (j < end) {
        int s0 = g_esrc[j];
        float2 r0 = hp[s0 * 32 + lane];
        float v0x = fmaf(r0.x, scx, shx), v0y = fmaf(r0.y, scy, shy);
        sxA += v0x; syA += v0y;
        qxA = fmaf(v0x, v0x, qxA);
        qyA = fmaf(v0y, v0y, qyA);
        mxx = fmaxf(mxx, v0x);
        mxy = fmaxf(mxy, v0y);
    }
    float sx = sxA + sxB, sy = syA + syB;
    float qx = qxA + qxB, qy = qyA + qyB;
    if (end == beg) { mxx = 0.f; mxy = 0.f; }
    float c = g_cfac[w];
    float inv = 1.f / c;
    float mex = sx * inv, mey = sy * inv;
    float vx = fmaxf(qx * inv - mex * mex, 0.f);
    float vy = fmaxf(qy * inv - mey * mey, 0.f);
    float2* bp = (float2*)(g_base + (size_t)w * 256);
    bp[lane]      = make_float2(sx, sy);
    bp[32 + lane] = make_float2(mxx, mxy);
    bp[64 + lane] = make_float2(mex, mey);
    bp[96 + lane] = make_float2(vx, vy);
}

// ---------------- 3xTF32 mma.sync GEMM + fused combine (affine residual) ----------------
#define AS_STRIDE 36
#define BS_STRIDE 200
#define SS_STRIDE 200
#define AH_OFFS 0
#define AL_OFFS (128 * AS_STRIDE)
#define BH_OFFS (2 * 128 * AS_STRIDE)
#define BL_OFFS (BH_OFFS + 32 * BS_STRIDE)
#define MMA_SMEM_FLOATS (128 * SS_STRIDE)
#define MMA_SMEM_BYTES (MMA_SMEM_FLOATS * 4)

__global__ void __launch_bounds__(384)
k_pna_mma(const float* __restrict__ Bh, const float* __restrict__ Bl,
          const float* __restrict__ mb) {
    extern __shared__ float sm[];
    float* Ash = sm + AH_OFFS;
    float* Asl = sm + AL_OFFS;
    float* Bsh = sm + BH_OFFS;
    float* Bsl = sm + BL_OFFS;
    int tid = threadIdx.x, wid = tid >> 5, lane = tid & 31;
    int gid = lane >> 2, tig = lane & 3;
    int row0 = blockIdx.x * 128;
    int mrow0 = (wid & 3) * 32;
    int ncol0 = (wid >> 2) * 64;

    float acc[2][8][4];
#pragma unroll
    for (int mt = 0; mt < 2; mt++)
#pragma unroll
        for (int nt = 0; nt < 8; nt++)
#pragma unroll
            for (int j = 0; j < 4; j++) acc[mt][nt][j] = 0.f;

#pragma unroll 1
    for (int kc = 0; kc < 8; kc++) {
        for (int i = tid; i < 1024; i += 384) {
            int r = i >> 3, c4 = i & 7;
            float4 v = *(const float4*)&g_base[(size_t)(row0 + r) * 256 + kc * 32 + c4 * 4];
            float4 h, l;
            h.x = tf32r(v.x); l.x = tf32r(v.x - h.x);
            h.y = tf32r(v.y); l.y = tf32r(v.y - h.y);
            h.z = tf32r(v.z); l.z = tf32r(v.z - h.z);
            h.w = tf32r(v.w); l.w = tf32r(v.w - h.w);
            *(float4*)&Ash[r * AS_STRIDE + c4 * 4] = h;
            *(float4*)&Asl[r * AS_STRIDE + c4 * 4] = l;
        }
        for (int i = tid; i < 1536; i += 384) {
            int r = i / 48, c4 = i % 48;
            size_t go = (size_t)(kc * 32 + r) * 192 + c4 * 4;
            *(float4*)&Bsh[r * BS_STRIDE + c4 * 4] = *(const float4*)&Bh[go];
            *(float4*)&Bsl[r * BS_STRIDE + c4 * 4] = *(const float4*)&Bl[go];
        }
        __syncthreads();
#pragma unroll
        for (int k8 = 0; k8 < 4; k8++) {
            int kb = k8 * 8;
            uint32_t ah[2][4], al[2][4];
#pragma unroll
            for (int mt = 0; mt < 2; mt++) {
                int mr = mrow0 + mt * 16 + gid;
                ah[mt][0] = __float_as_uint(Ash[mr * AS_STRIDE + kb + tig]);
                ah[mt][1] = __float_as_uint(Ash[(mr + 8) * AS_STRIDE + kb + tig]);
                ah[mt][2] = __float_as_uint(Ash[mr * AS_STRIDE + kb + tig + 4]);
                ah[mt][3] = __float_as_uint(Ash[(mr + 8) * AS_STRIDE + kb + tig + 4]);
                al[mt][0] = __float_as_uint(Asl[mr * AS_STRIDE + kb + tig]);
                al[mt][1] = __float_as_uint(Asl[(mr + 8) * AS_STRIDE + kb + tig]);
                al[mt][2] = __float_as_uint(Asl[mr * AS_STRIDE + kb + tig + 4]);
                al[mt][3] = __float_as_uint(Asl[(mr + 8) * AS_STRIDE + kb + tig + 4]);
            }
#pragma unroll
            for (int nt = 0; nt < 8; nt++) {
                int nc = ncol0 + nt * 8 + gid;
                uint32_t bh0 = __float_as_uint(Bsh[(kb + tig) * BS_STRIDE + nc]);
                uint32_t bh1 = __float_as_uint(Bsh[(kb + tig + 4) * BS_STRIDE + nc]);
                uint32_t bl0 = __float_as_uint(Bsl[(kb + tig) * BS_STRIDE + nc]);
                uint32_t bl1 = __float_as_uint(Bsl[(kb + tig + 4) * BS_STRIDE + nc]);
                mma1688(acc[0][nt], ah[0], bh0, bh1);
                mma1688(acc[0][nt], ah[0], bl0, bl1);
                mma1688(acc[0][nt], al[0], bh0, bh1);
                mma1688(acc[1][nt], ah[1], bh0, bh1);
                mma1688(acc[1][nt], ah[1], bl0, bl1);
                mma1688(acc[1][nt], al[1], bh0, bh1);
            }
        }
        __syncthreads();
    }

#pragma unroll
    for (int mt = 0; mt < 2; mt++) {
#pragma unroll
        for (int nt = 0; nt < 8; nt++) {
            int r = mrow0 + mt * 16 + gid;
            int c = ncol0 + nt * 8 + tig * 2;
            *(float2*)&sm[r * SS_STRIDE + c] = make_float2(acc[mt][nt][0], acc[mt][nt][1]);
            *(float2*)&sm[(r + 8) * SS_STRIDE + c] = make_float2(acc[mt][nt][2], acc[mt][nt][3]);
        }
    }
    __syncthreads();

    // combine epilogue: hC = affine(hB) + mb + S0 + (c/D)S1 + (D/c)S2
    for (int i = tid; i < 128 * 64; i += 384) {
        int r = i >> 6, d = i & 63;
        int row = row0 + r;
        if (row < Nn) {
            float cf = g_cfac[row];
            float aa = cf * (1.0f / DELTA);
            float b2 = DELTA / cf;
            const float* Sr = sm + r * SS_STRIDE;
            float x = fmaf(g_hB[(size_t)row * 64 + d], g_scale[d], g_shift[d]);
            float v = x + mb[d] + Sr[d] + aa * Sr[64 + d] + b2 * Sr[128 + d];
            g_hC[(size_t)row * 64 + d] = v;
        }
    }
}

// ---------------- fused nn + BN partials: hB = relu(relu(hC@W1t+b1)@W2t+b2) ----------------
// CTA 128 rows, 256 threads = 8 warps (4m x 2n), warp tile 32x32.
// Single weight buffer reused W1 -> W2 (smem 106.5KB -> 2 CTAs/SM).
#define FA_STRIDE 68
#define FW_STRIDE 72
#define F_ASH 0
#define F_ASL (128 * FA_STRIDE)              // 8704
#define F_WH  (2 * 128 * FA_STRIDE)          // 17408
#define F_WL  (F_WH + 64 * FW_STRIDE)        // 22016
#define F_SMEM_FLOATS (F_WL + 64 * FW_STRIDE)   // 26624
#define F_SMEM_BYTES (F_SMEM_FLOATS * 4)        // 106496

__global__ void __launch_bounds__(256)
k_nn_mma(const float* __restrict__ W1h, const float* __restrict__ W1l,
         const float* __restrict__ W2h, const float* __restrict__ W2l,
         const float* __restrict__ b1, const float* __restrict__ b2) {
    extern __shared__ float sm[];
    float* Ash = sm + F_ASH;
    float* Asl = sm + F_ASL;
    float* wh = sm + F_WH;
    float* wl = sm + F_WL;
    int tid = threadIdx.x, wid = tid >> 5, lane = tid & 31;
    int gid = lane >> 2, tig = lane & 3;
    int row0 = blockIdx.x * 128;
    int mrow0 = (wid & 3) * 32;
    int ncol0 = (wid >> 2) * 32;

    // load W1 into smem
    for (int i = tid; i < 4096; i += 256) {
        int k = i >> 6, d = i & 63;
        int so = k * FW_STRIDE + d;
        wh[so] = W1h[i];
        wl[so] = W1l[i];
    }
    // load A = g_hC tile, split hi/lo
    for (int i = tid; i < 2048; i += 256) {
        int r = i >> 4, c4 = i & 15;
        float4 v = *(const float4*)&g_hC[(size_t)(row0 + r) * 64 + c4 * 4];
        float4 h, l;
        h.x = tf32r(v.x); l.x = tf32r(v.x - h.x);
        h.y = tf32r(v.y); l.y = tf32r(v.y - h.y);
        h.z = tf32r(v.z); l.z = tf32r(v.z - h.z);
        h.w = tf32r(v.w); l.w = tf32r(v.w - h.w);
        *(float4*)&Ash[r * FA_STRIDE + c4 * 4] = h;
        *(float4*)&Asl[r * FA_STRIDE + c4 * 4] = l;
    }
    __syncthreads();

    float acc[2][4][4];

    // ---- stage 1: t = relu(A @ W1t + b1) ----
#pragma unroll
    for (int mt = 0; mt < 2; mt++)
#pragma unroll
        for (int nt = 0; nt < 4; nt++)
#pragma unroll
            for (int j = 0; j < 4; j++) acc[mt][nt][j] = 0.f;

#pragma unroll 1
    for (int k8 = 0; k8 < 8; k8++) {
        int kb = k8 * 8;
        uint32_t ah[2][4], al[2][4];
#pragma unroll
        for (int mt = 0; mt < 2; mt++) {
            int mr = mrow0 + mt * 16 + gid;
            ah[mt][0] = __float_as_uint(Ash[mr * FA_STRIDE + kb + tig]);
            ah[mt][1] = __float_as_uint(Ash[(mr + 8) * FA_STRIDE + kb + tig]);
            ah[mt][2] = __float_as_uint(Ash[mr * FA_STRIDE + kb + tig + 4]);
            ah[mt][3] = __float_as_uint(Ash[(mr + 8) * FA_STRIDE + kb + tig + 4]);
            al[mt][0] = __float_as_uint(Asl[mr * FA_STRIDE + kb + tig]);
            al[mt][1] = __float_as_uint(Asl[(mr + 8) * FA_STRIDE + kb + tig]);
            al[mt][2] = __float_as_uint(Asl[mr * FA_STRIDE + kb + tig + 4]);
            al[mt][3] = __float_as_uint(Asl[(mr + 8) * FA_STRIDE + kb + tig + 4]);
        }
#pragma unroll
        for (int nt = 0; nt < 4; nt++) {
            int nc = ncol0 + nt * 8 + gid;
            uint32_t bh0 = __float_as_uint(wh[(kb + tig) * FW_STRIDE + nc]);
            uint32_t bh1 = __float_as_uint(wh[(kb + tig + 4) * FW_STRIDE + nc]);
            uint32_t bl0 = __float_as_uint(wl[(kb + tig) * FW_STRIDE + nc]);
            uint32_t bl1 = __float_as_uint(wl[(kb + tig + 4) * FW_STRIDE + nc]);
            mma1688(acc[0][nt], ah[0], bh0, bh1);
            mma1688(acc[0][nt], ah[0], bl0, bl1);
            mma1688(acc[0][nt], al[0], bh0, bh1);
            mma1688(acc[1][nt], ah[1], bh0, bh1);
            mma1688(acc[1][nt], ah[1], bl0, bl1);
            mma1688(acc[1][nt], al[1], bh0, bh1);
        }
    }
    __syncthreads();   // done reading Ash/Asl and W1

    // load W2 into the same weight buffer
    for (int i = tid; i < 4096; i += 256) {
        int k = i >> 6, d = i & 63;
        int so = k * FW_STRIDE + d;
        wh[so] = W2h[i];
        wl[so] = W2l[i];
    }
    // relu + bias, re-split into Ash/Asl
#pragma unroll
    for (int mt = 0; mt < 2; mt++) {
#pragma unroll
        for (int nt = 0; nt < 4; nt++) {
            int r = mrow0 + mt * 16 + gid;
            int c = ncol0 + nt * 8 + tig * 2;
            float bb0 = b1[c], bb1 = b1[c + 1];
            float u0 = fmaxf(acc[mt][nt][0] + bb0, 0.f);
            float u1 = fmaxf(acc[mt][nt][1] + bb1, 0.f);
            float u2 = fmaxf(acc[mt][nt][2] + bb0, 0.f);
            float u3 = fmaxf(acc[mt][nt][3] + bb1, 0.f);
            float h0 = tf32r(u0), h1 = tf32r(u1), h2 = tf32r(u2), h3 = tf32r(u3);
            Ash[r * FA_STRIDE + c] = h0;
            Ash[r * FA_STRIDE + c + 1] = h1;
            Ash[(r + 8) * FA_STRIDE + c] = h2;
            Ash[(r + 8) * FA_STRIDE + c + 1] = h3;
            Asl[r * FA_STRIDE + c] = tf32r(u0 - h0);
            Asl[r * FA_STRIDE + c + 1] = tf32r(u1 - h1);
            Asl[(r + 8) * FA_STRIDE + c] = tf32r(u2 - h2);
            Asl[(r + 8) * FA_STRIDE + c + 1] = tf32r(u3 - h3);
        }
    }
    __syncthreads();

    // ---- stage 2: hB = relu(t @ W2t + b2) ----
#pragma unroll
    for (int mt = 0; mt < 2; mt++)
#pragma unroll
        for (int nt = 0; nt < 4; nt++)
#pragma unroll
            for (int j = 0; j < 4; j++) acc[mt][nt][j] = 0.f;

#pragma unroll 1
    for (int k8 = 0; k8 < 8; k8++) {
        int kb = k8 * 8;
        uint32_t ah[2][4], al[2][4];
#pragma unroll
        for (int mt = 0; mt < 2; mt++) {
            int mr = mrow0 + mt * 16 + gid;
            ah[mt][0] = __float_as_uint(Ash[mr * FA_STRIDE + kb + tig]);
            ah[mt][1] = __float_as_uint(Ash[(mr + 8) * FA_STRIDE + kb + tig]);
            ah[mt][2] = __float_as_uint(Ash[mr * FA_STRIDE + kb + tig + 4]);
            ah[mt][3] = __float_as_uint(Ash[(mr + 8) * FA_STRIDE + kb + tig + 4]);
            al[mt][0] = __float_as_uint(Asl[mr * FA_STRIDE + kb + tig]);
            al[mt][1] = __float_as_uint(Asl[(mr + 8) * FA_STRIDE + kb + tig]);
            al[mt][2] = __float_as_uint(Asl[mr * FA_STRIDE + kb + tig + 4]);
            al[mt][3] = __float_as_uint(Asl[(mr + 8) * FA_STRIDE + kb + tig + 4]);
        }
#pragma unroll
        for (int nt = 0; nt < 4; nt++) {
            int nc = ncol0 + nt * 8 + gid;
            uint32_t bh0 = __float_as_uint(wh[(kb + tig) * FW_STRIDE + nc]);
            uint32_t bh1 = __float_as_uint(wh[(kb + tig + 4) * FW_STRIDE + nc]);
            uint32_t bl0 = __float_as_uint(wl[(kb + tig) * FW_STRIDE + nc]);
            uint32_t bl1 = __float_as_uint(wl[(kb + tig + 4) * FW_STRIDE + nc]);
            mma1688(acc[0][nt], ah[0], bh0, bh1);
            mma1688(acc[0][nt], ah[0], bl0, bl1);
            mma1688(acc[0][nt], al[0], bh0, bh1);
            mma1688(acc[1][nt], ah[1], bh0, bh1);
            mma1688(acc[1][nt], ah[1], bl0, bl1);
            mma1688(acc[1][nt], al[1], bh0, bh1);
        }
    }
    __syncthreads();   // done reading Ash/Asl (stage-2 inputs); free for staging

    // epilogue: outer relu; write global + stage into smem for BN partials
#pragma unroll
    for (int mt = 0; mt < 2; mt++) {
#pragma unroll
        for (int nt = 0; nt < 4; nt++) {
            int r = mrow0 + mt * 16 + gid;
            int c = ncol0 + nt * 8 + tig * 2;
            float bb0 = b2[c], bb1 = b2[c + 1];
            int row = row0 + r;
            float v0 = fmaxf(acc[mt][nt][0] + bb0, 0.f);
            float v1 = fmaxf(acc[mt][nt][1] + bb1, 0.f);
            float v2 = fmaxf(acc[mt][nt][2] + bb0, 0.f);
            float v3 = fmaxf(acc[mt][nt][3] + bb1, 0.f);
            if (row < Nn) {
                *(float2*)&g_hB[(size_t)row * 64 + c] = make_float2(v0, v1);
            } else { v0 = 0.f; v1 = 0.f; }
            if (row + 8 < Nn) {
                *(float2*)&g_hB[(size_t)(row + 8) * 64 + c] = make_float2(v2, v3);
            } else { v2 = 0.f; v3 = 0.f; }
            Ash[r * FA_STRIDE + c] = v0;
            Ash[r * FA_STRIDE + c + 1] = v1;
            Ash[(r + 8) * FA_STRIDE + c] = v2;
            Ash[(r + 8) * FA_STRIDE + c + 1] = v3;
        }
    }
    __syncthreads();

    // deterministic per-CTA BN partials: sum (tid<64) / sumsq (64<=tid<128)
    if (tid < 128) {
        int f = tid & 63;
        bool sq = tid >= 64;
        float s = 0.f;
#pragma unroll 4
        for (int r = 0; r < 128; r++) {
            float v = Ash[r * FA_STRIDE + f];
            s += sq ? v * v : v;
        }
        g_part[blockIdx.x * 128 + tid] = s;
    }
}

// ---------------- BN finalize: reduce 782 per-CTA partials ----------------
__global__ void __launch_bounds__(256)
k_bnfin(const float* __restrict__ gamma, const float* __restrict__ beta) {
    __shared__ float red[256];
    int tid = threadIdx.x;
    int f = tid & 63, g = tid >> 6;
    bool sq = (g >= 2);
    int c0 = (g & 1) ? 391 : 0;
    int c1 = (g & 1) ? NBMMA : 391;
    const float* p = g_part + (sq ? 64 : 0) + f;
    float s = 0.f;
#pragma unroll 4
    for (int c = c0; c < c1; c++) s += p[c * 128];
    red[tid] = s;
    __syncthreads();
    if (tid < 64) {
        float s1 = red[tid] + red[64 + tid];
        float q1 = red[128 + tid] + red[192 + tid];
        float mean = s1 * (1.0f / Nn);
        float var = q1 * (1.0f / Nn) - mean * mean;
        float sc = gamma[tid] * rsqrtf(var + BN_EPS);
        g_scale[tid] = sc;
        g_shift[tid] = fmaf(-mean, sc, beta[tid]);
    }
}

// ---------------- pooling + head ----------------
__global__ void k_bounds(const int* __restrict__ batch) {
    int g = blockIdx.x * blockDim.x + threadIdx.x;
    if (g > Gg) return;
    if (g == Gg) { g_bstart[Gg] = Nn; return; }
    int lo = 0, hi = Nn;
    while (lo < hi) {
        int mid = (lo + hi) >> 1;
        if (batch[mid] < g) lo = mid + 1; else hi = mid;
    }
    g_bstart[g] = lo;
}
__global__ void k_pool() {
    int g = blockIdx.x, d = threadIdx.x;
    int r0 = g_bstart[g], r1 = g_bstart[g + 1];
    float sc = g_scale[d], sh = g_shift[d];
    float s = 0.f;
    for (int r = r0; r < r1; r++) s += fmaf(g_hB[r * 64 + d], sc, sh);
    g_gpool[g * 64 + d] = s;
}
__global__ void k_head(const float* __restrict__ fc1b, const float* __restrict__ fc2b,
                       float* __restrict__ out) {
    __shared__ float gsm[64], tsm[64];
    int g = blockIdx.x, d = threadIdx.x;
    gsm[d] = g_gpool[g * 64 + d];
    __syncthreads();
    float acc = fc1b[d];
    for (int k = 0; k < 64; k++) acc = fmaf(gsm[k], g_fc1Wt[k * 64 + d], acc);
    tsm[d] = fmaxf(acc, 0.f);
    __syncthreads();
    if (d < OUTD) {
        float a2 = fc2b[d];
        for (int k = 0; k < 64; k++) a2 = fmaf(tsm[k], g_fc2Wt[k * 16 + d], a2);
        out[g * OUTD + d] = a2;
    }
}

// ---------------- host ----------------
extern "C" void kernel_launch(void* const* d_in, const int* in_sizes, int n_in,
                              void* d_out, int out_size) {
    const float* x    = (const float*)d_in[0];
    const int*   ei   = (const int*)d_in[1];
    const int*   src  = ei;
    const int*   dst  = ei + Ee;
    const int*   batch = (const int*)d_in[2];
    const float* encW = (const float*)d_in[3];
    const float* encb = (const float*)d_in[4];
    const float* nnW1 = (const float*)d_in[5];
    const float* nnb1 = (const float*)d_in[6];
    const float* nnW2 = (const float*)d_in[7];
    const float* nnb2 = (const float*)d_in[8];
    const float* mlpW = (const float*)d_in[9];
    const float* mlpb = (const float*)d_in[10];
    const float* bnG  = (const float*)d_in[11];
    const float* bnB  = (const float*)d_in[12];
    const float* fc1W = (const float*)d_in[13];
    const float* fc1b = (const float*)d_in[14];
    const float* fc2W = (const float*)d_in[15];
    const float* fc2b = (const float*)d_in[16];
    float* out = (float*)d_out;

    float *p_hB, *p_encWt, *p_fc1Wt, *p_mlpBh, *p_mlpBl;
    float *p_W1h, *p_W1l, *p_W2h, *p_W2l;
    cudaGetSymbolAddress((void**)&p_hB, g_hB);
    cudaGetSymbolAddress((void**)&p_encWt, g_encWt);
    cudaGetSymbolAddress((void**)&p_fc1Wt, g_fc1Wt);
    cudaGetSymbolAddress((void**)&p_mlpBh, g_mlpBh);
    cudaGetSymbolAddress((void**)&p_mlpBl, g_mlpBl);
    cudaGetSymbolAddress((void**)&p_W1h, g_nnW1h);
    cudaGetSymbolAddress((void**)&p_W1l, g_nnW1l);
    cudaGetSymbolAddress((void**)&p_W2h, g_nnW2h);
    cudaGetSymbolAddress((void**)&p_W2l, g_nnW2l);

    cudaFuncSetAttribute(k_pna_mma, cudaFuncAttributeMaxDynamicSharedMemorySize, MMA_SMEM_BYTES);
    cudaFuncSetAttribute(k_nn_mma, cudaFuncAttributeMaxDynamicSharedMemorySize, F_SMEM_BYTES);

    const int NB_SCAN = (Nn + 1023) / 1024;

    // CSR build
    k_zero_deg<<<(Nn + 255) / 256, 256>>>();
    k_count<<<(Ee + 255) / 256, 256>>>(dst);
    k_scan_block<<<NB_SCAN, 1024>>>();
    k_scan_tops<<<1, 1>>>(NB_SCAN);
    k_rowptr<<<(Nn + 255) / 256, 256>>>();
    k_scatter<<<(Ee + 255) / 256, 256>>>(src, dst);
    k_sortrows<<<(Nn + 255) / 256, 256>>>();

    // weight prep (k_tfc2 also sets identity affine for layer 0)
    k_t64<<<(4096 + 255) / 256, 256>>>(encW, p_encWt, 1);
    k_t64<<<(4096 + 255) / 256, 256>>>(fc1W, p_fc1Wt, 1);
    k_t64split<<<(5 * 4096 + 255) / 256, 256>>>(nnW1, p_W1h, p_W1l, 5);
    k_t64split<<<(5 * 4096 + 255) / 256, 256>>>(nnW2, p_W2h, p_W2l, 5);
    k_tmlpB<<<(NL * 256 * 192 + 255) / 256, 256>>>(mlpW);
    k_tfc2<<<(Dd * OUTD + 255) / 256, 256>>>(fc2W);

    const int NBLIN = NnP / 64;

    k_lin64<false><<<NBLIN, 64>>>(x, p_encWt, encb, p_hB);

    for (int i = 0; i < NL; i++) {
        k_agg<<<(Nn * 32 + 255) / 256, 256>>>();
        k_pna_mma<<<NBMMA, 384, MMA_SMEM_BYTES>>>(p_mlpBh + i * 49152, p_mlpBl + i * 49152, mlpb + i * Dd);
        k_nn_mma<<<NBMMA, 256, F_SMEM_BYTES>>>(p_W1h + i * 4096, p_W1l + i * 4096,
                                               p_W2h + i * 4096, p_W2l + i * 4096,
                                               nnb1 + i * Dd, nnb2 + i * Dd);
        k_bnfin<<<1, 256>>>(bnG + i * Dd, bnB + i * Dd);
    }

    k_bounds<<<(Gg + 1 + 255) / 256, 256>>>(batch);
    k_pool<<<Gg, 64>>>();
    k_head<<<Gg, 64>>>(fc1b, fc2b, out);
}

// round 8
// speedup vs baseline: 1.2903x; 1.2525x over previous
#include <cuda_runtime.h>
#include <cfloat>
#include <cstdint>

#define Nn 100000
#define NnP 100096          // multiple of 128 (MMA tile)
#define Ee 1600000
#define Dd 64
#define Gg 512
#define OUTD 16
#define NL 5
#define DELTA 2.5749f
#define BN_EPS 1e-5f
#define NBMMA (NnP / 128)   // 782

// ---------------- static device scratch ----------------
static __device__ float g_hB[NnP * Dd];        // layer output (pre-BN)
static __device__ float g_hC[NnP * Dd];        // combine intermediate
static __device__ float g_baseH[NnP * 256];    // [sum|max|mean|var] tf32 hi
static __device__ float g_baseL[NnP * 256];    // tf32 lo residual
static __device__ float g_cfac[NnP];
static __device__ int   g_deg[Nn];
static __device__ int   g_sc[Nn];
static __device__ int   g_bsum[128];
static __device__ int   g_rowptr[Nn + 1];
static __device__ int   g_cursor[Nn];
static __device__ int   g_esrc[Ee];
static __device__ float g_part[NBMMA * 128];   // per-CTA BN partials
static __device__ float g_scale[Dd];
static __device__ float g_shift[Dd];
static __device__ int   g_bstart[Gg + 1];
static __device__ float g_gpool[Gg * Dd];
static __device__ float g_encWt[Dd * Dd];
static __device__ float g_nnW1h[NL * Dd * Dd];  // [k][d] tf32 hi
static __device__ float g_nnW1l[NL * Dd * Dd];  // [k][d] tf32 lo
static __device__ float g_nnW2h[NL * Dd * Dd];
static __device__ float g_nnW2l[NL * Dd * Dd];
static __device__ float g_mlpBh[NL * 256 * 192];  // [k][n], tf32 hi
static __device__ float g_mlpBl[NL * 256 * 192];  // [k][n], tf32 lo residual
static __device__ float g_fc1Wt[Dd * Dd];
static __device__ float g_fc2Wt[Dd * OUTD];

__device__ __forceinline__ float tf32r(float x) {
    float y;
    asm("cvt.rna.tf32.f32 %0, %1;" : "=f"(y) : "f"(x));
    return y;
}
__device__ __forceinline__ void mma1688(float* c, const uint32_t* a, uint32_t b0, uint32_t b1) {
    asm volatile(
        "mma.sync.aligned.m16n8k8.row.col.f32.tf32.tf32.f32 "
        "{%0,%1,%2,%3}, {%4,%5,%6,%7}, {%8,%9}, {%0,%1,%2,%3};"
        : "+f"(c[0]), "+f"(c[1]), "+f"(c[2]), "+f"(c[3])
        : "r"(a[0]), "r"(a[1]), "r"(a[2]), "r"(a[3]), "r"(b0), "r"(b1));
}
__device__ __forceinline__ uint32_t smem_u32(const void* p) {
    uint32_t a;
    asm("{ .reg .u64 t; cvta.to.shared.u64 t, %1; cvt.u32.u64 %0, t; }" : "=r"(a) : "l"(p));
    return a;
}
__device__ __forceinline__ void cp16(uint32_t d, const void* s) {
    asm volatile("cp.async.cg.shared.global [%0], [%1], 16;" :: "r"(d), "l"(s));
}
#define CP_COMMIT() asm volatile("cp.async.commit_group;" ::: "memory")
#define CP_WAIT(n)  asm volatile("cp.async.wait_group %0;" :: "n"(n) : "memory")

// ---------------- CSR build ----------------
__global__ void k_zero_deg() {
    int i = blockIdx.x * blockDim.x + threadIdx.x;
    if (i < Nn) g_deg[i] = 0;
}
__global__ void k_count(const int* __restrict__ dst) {
    int e = blockIdx.x * blockDim.x + threadIdx.x;
    if (e < Ee) atomicAdd(&g_deg[dst[e]], 1);
}
__global__ void k_scan_block() {
    __shared__ int sm[1024];
    int i = blockIdx.x * 1024 + threadIdx.x;
    int v = (i < Nn) ? g_deg[i] : 0;
    sm[threadIdx.x] = v;
    __syncthreads();
    for (int off = 1; off < 1024; off <<= 1) {
        int t = 0;
        if (threadIdx.x >= off) t = sm[threadIdx.x - off];
        __syncthreads();
        sm[threadIdx.x] += t;
        __syncthreads();
    }
    if (i < Nn) g_sc[i] = sm[threadIdx.x];
    if (threadIdx.x == 1023) g_bsum[blockIdx.x] = sm[1023];
}
__global__ void k_scan_tops(int nb) {
    if (threadIdx.x == 0 && blockIdx.x == 0) {
        int run = 0;
        for (int b = 0; b < nb; b++) { int t = g_bsum[b]; g_bsum[b] = run; run += t; }
    }
}
__global__ void k_rowptr() {
    int i = blockIdx.x * blockDim.x + threadIdx.x;
    if (i < Nn) {
        int rp = g_sc[i] - g_deg[i] + g_bsum[i >> 10];
        g_rowptr[i] = rp;
        g_cursor[i] = rp;
        g_cfac[i] = fmaxf((float)g_deg[i], 1.0f);
    }
    if (i == 0) g_rowptr[Nn] = Ee;
}
__global__ void k_scatter(const int* __restrict__ src, const int* __restrict__ dst) {
    int e = blockIdx.x * blockDim.x + threadIdx.x;
    if (e < Ee) {
        int p = atomicAdd(&g_cursor[dst[e]], 1);
        g_esrc[p] = src[e];
    }
}
__global__ void k_sortrows() {
    int n = blockIdx.x * blockDim.x + threadIdx.x;
    if (n >= Nn) return;
    int beg = g_rowptr[n], end = g_rowptr[n + 1];
    int deg = end - beg;
    if (deg <= 1) return;
    if (deg <= 128) {
        int buf[128];
        for (int i = 0; i < deg; i++) buf[i] = g_esrc[beg + i];
        for (int i = 1; i < deg; i++) {
            int v = buf[i];
            int j = i - 1;
            while (j >= 0 && buf[j] > v) { buf[j + 1] = buf[j]; j--; }
            buf[j + 1] = v;
        }
        for (int i = 0; i < deg; i++) g_esrc[beg + i] = buf[i];
    } else {
        for (int i = beg + 1; i < end; i++) {
            int v = g_esrc[i];
            int j = i - 1;
            while (j >= beg && g_esrc[j] > v) { g_esrc[j + 1] = g_esrc[j]; j--; }
            g_esrc[j + 1] = v;
        }
    }
}

// ---------------- weight prep ----------------
__global__ void k_t64(const float* __restrict__ W, float* __restrict__ Wt, int nm) {
    int idx = blockIdx.x * blockDim.x + threadIdx.x;
    if (idx >= nm * 4096) return;
    int m = idx >> 12, r = idx & 4095;
    int d = r >> 6, k = r & 63;
    Wt[(m << 12) + (k << 6) + d] = W[idx];
}
__global__ void k_t64split(const float* __restrict__ W, float* __restrict__ Wh,
                           float* __restrict__ Wl, int nm) {
    int idx = blockIdx.x * blockDim.x + threadIdx.x;
    if (idx >= nm * 4096) return;
    int m = idx >> 12, r = idx & 4095;
    int d = r >> 6, k = r & 63;
    float w = W[idx];
    float h = tf32r(w);
    Wh[(m << 12) + (k << 6) + d] = h;
    Wl[(m << 12) + (k << 6) + d] = tf32r(w - h);
}
__global__ void k_tmlpB(const float* __restrict__ W) {
    int idx = blockIdx.x * blockDim.x + threadIdx.x;
    if (idx >= NL * 256 * 192) return;
    int m = idx / 49152, r = idx % 49152;
    int k = r / 192, n = r % 192;
    int d = n & 63, b = n >> 6;
    float w = W[m * 49152 + d * 768 + b * 256 + k];
    float h = tf32r(w);
    g_mlpBh[idx] = h;
    g_mlpBl[idx] = tf32r(w - h);
}
// also initializes identity affine for layer 0
__global__ void k_tfc2(const float* __restrict__ W) {
    int idx = blockIdx.x * blockDim.x + threadIdx.x;
    if (idx < 64) { g_scale[idx] = 1.0f; g_shift[idx] = 0.0f; }
    if (idx >= Dd * OUTD) return;
    int o = idx >> 6, k = idx & 63;
    g_fc2Wt[k * 16 + o] = W[idx];
}

// ---------------- 64x64 linear (encoder only) ----------------
template <bool RELU>
__global__ void __launch_bounds__(64) k_lin64(const float* __restrict__ A,
                                              const float* __restrict__ Wt,
                                              const float* __restrict__ b,
                                              float* __restrict__ C) {
    __shared__ float4 Asm[64][16];
    int row0 = blockIdx.x * 64, tid = threadIdx.x;
    for (int t = tid; t < 1024; t += 64) {
        int r = t >> 4, c = t & 15;
        float4 v = make_float4(0.f, 0.f, 0.f, 0.f);
        if (row0 + r < Nn) v = ((const float4*)A)[(row0 + r) * 16 + c];
        Asm[r][c] = v;
    }
    __syncthreads();
    float acc[64];
#pragma unroll
    for (int r = 0; r < 64; r++) acc[r] = 0.f;
#pragma unroll 1
    for (int k4 = 0; k4 < 16; k4++) {
        float w0 = Wt[(k4 * 4 + 0) * 64 + tid];
        float w1 = Wt[(k4 * 4 + 1) * 64 + tid];
        float w2 = Wt[(k4 * 4 + 2) * 64 + tid];
        float w3 = Wt[(k4 * 4 + 3) * 64 + tid];
#pragma unroll
        for (int r = 0; r < 64; r++) {
            float4 a = Asm[r][k4];
            float t0 = fmaf(a.x, w0, acc[r]);
            t0 = fmaf(a.y, w1, t0);
            t0 = fmaf(a.z, w2, t0);
            acc[r] = fmaf(a.w, w3, t0);
        }
    }
    float bb = b[tid];
    for (int r = 0; r < 64; r++) {
        if (row0 + r < Nn) {
            float v = acc[r] + bb;
            if (RELU) v = fmaxf(v, 0.f);
            C[(row0 + r) * 64 + tid] = v;
        }
    }
}

// ---------------- PNA aggregation (warp/node, BN-affine on the fly, tf32-split out) ----------------
__global__ void k_agg() {
    int gt = blockIdx.x * blockDim.x + threadIdx.x;
    int w = gt >> 5, lane = gt & 31;
    if (w >= Nn) return;
    int beg = g_rowptr[w], end = g_rowptr[w + 1];
    const float2* hp = (const float2*)g_hB;
    float scx = g_scale[2 * lane], scy = g_scale[2 * lane + 1];
    float shx = g_shift[2 * lane], shy = g_shift[2 * lane + 1];
    float sxA = 0.f, syA = 0.f, qxA = 0.f, qyA = 0.f;
    float sxB = 0.f, syB = 0.f, qxB = 0.f, qyB = 0.f;
    float mxx = -FLT_MAX, mxy = -FLT_MAX;
    int j = beg;
    for (; j + 1 < end; j += 2) {
        int s0 = g_esrc[j];
        int s1 = g_esrc[j + 1];
        float2 r0 = hp[s0 * 32 + lane];
        float2 r1 = hp[s1 * 32 + lane];
        float v0x = fmaf(r0.x, scx, shx), v0y = fmaf(r0.y, scy, shy);
        float v1x = fmaf(r1.x, scx, shx), v1y = fmaf(r1.y, scy, shy);
        sxA += v0x; syA += v0y;
        qxA = fmaf(v0x, v0x, qxA);
        qyA = fmaf(v0y, v0y, qyA);
        mxx = fmaxf(mxx, v0x);
        mxy = fmaxf(mxy, v0y);
        sxB += v1x; syB += v1y;
        qxB = fmaf(v1x, v1x, qxB);
        qyB = fmaf(v1y, v1y, qyB);
        mxx = fmaxf(mxx, v1x);
        mxy = fmaxf(mxy, v1y);
    }
    if (j < end) {
        int s0 = g_esrc[j];
        float2 r0 = hp[s0 * 32 + lane];
        float v0x = fmaf(r0.x, scx, shx), v0y = fmaf(r0.y, scy, shy);
        sxA += v0x; syA += v0y;
        qxA = fmaf(v0x, v0x, qxA);
        qyA = fmaf(v0y, v0y, qyA);
        mxx = fmaxf(mxx, v0x);
        mxy = fmaxf(mxy, v0y);
    }
    float sx = sxA + sxB, sy = syA + syB;
    float qx = qxA + qxB, qy = qyA + qyB;
    if (end == beg) { mxx = 0.f; mxy = 0.f; }
    float c = g_cfac[w];
    float inv = 1.f / c;
    float mex = sx * inv, mey = sy * inv;
    float vx = fmaxf(qx * inv - mex * mex, 0.f);
    float vy = fmaxf(qy * inv - mey * mey, 0.f);
    float2* bpH = (float2*)(g_baseH + (size_t)w * 256);
    float2* bpL = (float2*)(g_baseL + (size_t)w * 256);
    float hx, hy;
    hx = tf32r(sx);  hy = tf32r(sy);
    bpH[lane]      = make_float2(hx, hy);
    bpL[lane]      = make_float2(tf32r(sx - hx), tf32r(sy - hy));
    hx = tf32r(mxx); hy = tf32r(mxy);
    bpH[32 + lane] = make_float2(hx, hy);
    bpL[32 + lane] = make_float2(tf32r(mxx - hx), tf32r(mxy - hy));
    hx = tf32r(mex); hy = tf32r(mey);
    bpH[64 + lane] = make_float2(hx, hy);
    bpL[64 + lane] = make_float2(tf32r(mex - hx), tf32r(mey - hy));
    hx = tf32r(vx);  hy = tf32r(vy);
    bpH[96 + lane] = make_float2(hx, hy);
    bpL[96 + lane] = make_float2(tf32r(vx - hx), tf32r(vy - hy));
}

// ---------------- 3xTF32 mma.sync GEMM, cp.async double-buffered, fused combine ----------------
#define AS_STRIDE 36
#define BS_STRIDE 200
#define SS_STRIDE 200
#define P_AH 0
#define P_AL 4608
#define P_BH 9216
#define P_BL 15616
#define PSTG 22016                         // floats per stage
#define PNA_SMEM_FLOATS (2 * PSTG)         // 44032
#define PNA_SMEM_BYTES (PNA_SMEM_FLOATS * 4)  // 176128

__global__ void __launch_bounds__(384)
k_pna_mma(const float* __restrict__ Bh, const float* __restrict__ Bl,
          const float* __restrict__ mb) {
    extern __shared__ float sm[];
    uint32_t sb = smem_u32(sm);
    int tid = threadIdx.x, wid = tid >> 5, lane = tid & 31;
    int gid = lane >> 2, tig = lane & 3;
    int row0 = blockIdx.x * 128;
    int mrow0 = (wid & 3) * 32;
    int ncol0 = (wid >> 2) * 64;

    // async load of one kc stage into buffer `buf`
    auto load_stage = [&](int kc, int buf) {
        uint32_t aH = sb + (uint32_t)(buf * PSTG + P_AH) * 4;
        uint32_t aL = sb + (uint32_t)(buf * PSTG + P_AL) * 4;
        uint32_t bH = sb + (uint32_t)(buf * PSTG + P_BH) * 4;
        uint32_t bL = sb + (uint32_t)(buf * PSTG + P_BL) * 4;
        for (int i = tid; i < 1024; i += 384) {
            int r = i >> 3, c4 = i & 7;
            uint32_t off = (uint32_t)(r * AS_STRIDE + c4 * 4) * 4;
            size_t go = (size_t)(row0 + r) * 256 + kc * 32 + c4 * 4;
            cp16(aH + off, &g_baseH[go]);
            cp16(aL + off, &g_baseL[go]);
        }
        for (int i = tid; i < 1536; i += 384) {
            int r = i / 48, c4 = i % 48;
            uint32_t off = (uint32_t)(r * BS_STRIDE + c4 * 4) * 4;
            size_t go = (size_t)(kc * 32 + r) * 192 + c4 * 4;
            cp16(bH + off, &Bh[go]);
            cp16(bL + off, &Bl[go]);
        }
    };

    float acc[2][8][4];
#pragma unroll
    for (int mt = 0; mt < 2; mt++)
#pragma unroll
        for (int nt = 0; nt < 8; nt++)
#pragma unroll
            for (int j = 0; j < 4; j++) acc[mt][nt][j] = 0.f;

    load_stage(0, 0);
    CP_COMMIT();

#pragma unroll 1
    for (int kc = 0; kc < 8; kc++) {
        if (kc < 7) {
            load_stage(kc + 1, (kc + 1) & 1);
            CP_COMMIT();
            CP_WAIT(1);
        } else {
            CP_WAIT(0);
        }
        __syncthreads();
        const float* Ash = sm + (kc & 1) * PSTG + P_AH;
        const float* Asl = sm + (kc & 1) * PSTG + P_AL;
        const float* Bsh = sm + (kc & 1) * PSTG + P_BH;
        const float* Bsl = sm + (kc & 1) * PSTG + P_BL;
#pragma unroll
        for (int k8 = 0; k8 < 4; k8++) {
            int kb = k8 * 8;
            uint32_t ah[2][4], al[2][4];
#pragma unroll
            for (int mt = 0; mt < 2; mt++) {
                int mr = mrow0 + mt * 16 + gid;
                ah[mt][0] = __float_as_uint(Ash[mr * AS_STRIDE + kb + tig]);
                ah[mt][1] = __float_as_uint(Ash[(mr + 8) * AS_STRIDE + kb + tig]);
                ah[mt][2] = __float_as_uint(Ash[mr * AS_STRIDE + kb + tig + 4]);
                ah[mt][3] = __float_as_uint(Ash[(mr + 8) * AS_STRIDE + kb + tig + 4]);
                al[mt][0] = __float_as_uint(Asl[mr * AS_STRIDE + kb + tig]);
                al[mt][1] = __float_as_uint(Asl[(mr + 8) * AS_STRIDE + kb + tig]);
                al[mt][2] = __float_as_uint(Asl[mr * AS_STRIDE + kb + tig + 4]);
                al[mt][3] = __float_as_uint(Asl[(mr + 8) * AS_STRIDE + kb + tig + 4]);
            }
#pragma unroll
            for (int nt = 0; nt < 8; nt++) {
                int nc = ncol0 + nt * 8 + gid;
                uint32_t bh0 = __float_as_uint(Bsh[(kb + tig) * BS_STRIDE + nc]);
                uint32_t bh1 = __float_as_uint(Bsh[(kb + tig + 4) * BS_STRIDE + nc]);
                uint32_t bl0 = __float_as_uint(Bsl[(kb + tig) * BS_STRIDE + nc]);
                uint32_t bl1 = __float_as_uint(Bsl[(kb + tig + 4) * BS_STRIDE + nc]);
                mma1688(acc[0][nt], ah[0], bh0, bh1);
                mma1688(acc[0][nt], ah[0], bl0, bl1);
                mma1688(acc[0][nt], al[0], bh0, bh1);
                mma1688(acc[1][nt], ah[1], bh0, bh1);
                mma1688(acc[1][nt], ah[1], bl0, bl1);
                mma1688(acc[1][nt], al[1], bh0, bh1);
            }
        }
        __syncthreads();
    }

    // stage S into smem (reuse stage buffers: 25600 <= 44032 floats)
#pragma unroll
    for (int mt = 0; mt < 2; mt++) {
#pragma unroll
        for (int nt = 0; nt < 8; nt++) {
            int r = mrow0 + mt * 16 + gid;
            int c = ncol0 + nt * 8 + tig * 2;
            *(float2*)&sm[r * SS_STRIDE + c] = make_float2(acc[mt][nt][0], acc[mt][nt][1]);
            *(float2*)&sm[(r + 8) * SS_STRIDE + c] = make_float2(acc[mt][nt][2], acc[mt][nt][3]);
        }
    }
    __syncthreads();

    // combine epilogue: hC = affine(hB) + mb + S0 + (c/D)S1 + (D/c)S2
    for (int i = tid; i < 128 * 64; i += 384) {
        int r = i >> 6, d = i & 63;
        int row = row0 + r;
        if (row < Nn) {
            float cf = g_cfac[row];
            float aa = cf * (1.0f / DELTA);
            float b2 = DELTA / cf;
            const float* Sr = sm + r * SS_STRIDE;
            float x = fmaf(g_hB[(size_t)row * 64 + d], g_scale[d], g_shift[d]);
            float v = x + mb[d] + Sr[d] + aa * Sr[64 + d] + b2 * Sr[128 + d];
            g_hC[(size_t)row * 64 + d] = v;
        }
    }
}

// ---------------- fused nn + BN partials: hB = relu(relu(hC@W1t+b1)@W2t+b2) ----------------
#define FA_STRIDE 68
#define FW_STRIDE 72
#define F_ASH 0
#define F_ASL (128 * FA_STRIDE)              // 8704
#define F_WH  (2 * 128 * FA_STRIDE)          // 17408
#define F_WL  (F_WH + 64 * FW_STRIDE)        // 22016
#define F_SMEM_FLOATS (F_WL + 64 * FW_STRIDE)   // 26624
#define F_SMEM_BYTES (F_SMEM_FLOATS * 4)        // 106496

__global__ void __launch_bounds__(256)
k_nn_mma(const float* __restrict__ W1h, const float* __restrict__ W1l,
         const float* __restrict__ W2h, const float* __restrict__ W2l,
         const float* __restrict__ b1, const float* __restrict__ b2) {
    extern __shared__ float sm[];
    uint32_t sb = smem_u32(sm);
    float* Ash = sm + F_ASH;
    float* Asl = sm + F_ASL;
    float* wh = sm + F_WH;
    float* wl = sm + F_WL;
    uint32_t whA = sb + F_WH * 4, wlA = sb + F_WL * 4;
    int tid = threadIdx.x, wid = tid >> 5, lane = tid & 31;
    int gid = lane >> 2, tig = lane & 3;
    int row0 = blockIdx.x * 128;
    int mrow0 = (wid & 3) * 32;
    int ncol0 = (wid >> 2) * 32;

    // async prefetch W1 while we split A
    for (int i = tid; i < 1024; i += 256) {
        int k = i >> 4, c4 = i & 15;
        uint32_t off = (uint32_t)(k * FW_STRIDE + c4 * 4) * 4;
        cp16(whA + off, &W1h[i * 4]);
        cp16(wlA + off, &W1l[i * 4]);
    }
    CP_COMMIT();

    // load A = g_hC tile, split hi/lo
    for (int i = tid; i < 2048; i += 256) {
        int r = i >> 4, c4 = i & 15;
        float4 v = *(const float4*)&g_hC[(size_t)(row0 + r) * 64 + c4 * 4];
        float4 h, l;
        h.x = tf32r(v.x); l.x = tf32r(v.x - h.x);
        h.y = tf32r(v.y); l.y = tf32r(v.y - h.y);
        h.z = tf32r(v.z); l.z = tf32r(v.z - h.z);
        h.w = tf32r(v.w); l.w = tf32r(v.w - h.w);
        *(float4*)&Ash[r * FA_STRIDE + c4 * 4] = h;
        *(float4*)&Asl[r * FA_STRIDE + c4 * 4] = l;
    }
    CP_WAIT(0);
    __syncthreads();

    float acc[2][4][4];

    // ---- stage 1: t = relu(A @ W1t + b1) ----
#pragma unroll
    for (int mt = 0; mt < 2; mt++)
#pragma unroll
        for (int nt = 0; nt < 4; nt++)
#pragma unroll
            for (int j = 0; j < 4; j++) acc[mt][nt][j] = 0.f;

#pragma unroll 1
    for (int k8 = 0; k8 < 8; k8++) {
        int kb = k8 * 8;
        uint32_t ah[2][4], al[2][4];
#pragma unroll
        for (int mt = 0; mt < 2; mt++) {
            int mr = mrow0 + mt * 16 + gid;
            ah[mt][0] = __float_as_uint(Ash[mr * FA_STRIDE + kb + tig]);
            ah[mt][1] = __float_as_uint(Ash[(mr + 8) * FA_STRIDE + kb + tig]);
            ah[mt][2] = __float_as_uint(Ash[mr * FA_STRIDE + kb + tig + 4]);
            ah[mt][3] = __float_as_uint(Ash[(mr + 8) * FA_STRIDE + kb + tig + 4]);
            al[mt][0] = __float_as_uint(Asl[mr * FA_STRIDE + kb + tig]);
            al[mt][1] = __float_as_uint(Asl[(mr + 8) * FA_STRIDE + kb + tig]);
            al[mt][2] = __float_as_uint(Asl[mr * FA_STRIDE + kb + tig + 4]);
            al[mt][3] = __float_as_uint(Asl[(mr + 8) * FA_STRIDE + kb + tig + 4]);
        }
#pragma unroll
        for (int nt = 0; nt < 4; nt++) {
            int nc = ncol0 + nt * 8 + gid;
            uint32_t bh0 = __float_as_uint(wh[(kb + tig) * FW_STRIDE + nc]);
            uint32_t bh1 = __float_as_uint(wh[(kb + tig + 4) * FW_STRIDE + nc]);
            uint32_t bl0 = __float_as_uint(wl[(kb + tig) * FW_STRIDE + nc]);
            uint32_t bl1 = __float_as_uint(wl[(kb + tig + 4) * FW_STRIDE + nc]);
            mma1688(acc[0][nt], ah[0], bh0, bh1);
            mma1688(acc[0][nt], ah[0], bl0, bl1);
            mma1688(acc[0][nt], al[0], bh0, bh1);
            mma1688(acc[1][nt], ah[1], bh0, bh1);
            mma1688(acc[1][nt], ah[1], bl0, bl1);
            mma1688(acc[1][nt], al[1], bh0, bh1);
        }
    }
    __syncthreads();   // done reading Ash/Asl and W1

    // async load W2 into the same weight buffer; hide under relu-resplit
    for (int i = tid; i < 1024; i += 256) {
        int k = i >> 4, c4 = i & 15;
        uint32_t off = (uint32_t)(k * FW_STRIDE + c4 * 4) * 4;
        cp16(whA + off, &W2h[i * 4]);
        cp16(wlA + off, &W2l[i * 4]);
    }
    CP_COMMIT();

    // relu + bias, re-split into Ash/Asl
#pragma unroll
    for (int mt = 0; mt < 2; mt++) {
#pragma unroll
        for (int nt = 0; nt < 4; nt++) {
            int r = mrow0 + mt * 16 + gid;
            int c = ncol0 + nt * 8 + tig * 2;
            float bb0 = b1[c], bb1 = b1[c + 1];
            float u0 = fmaxf(acc[mt][nt][0] + bb0, 0.f);
            float u1 = fmaxf(acc[mt][nt][1] + bb1, 0.f);
            float u2 = fmaxf(acc[mt][nt][2] + bb0, 0.f);
            float u3 = fmaxf(acc[mt][nt][3] + bb1, 0.f);
            float h0 = tf32r(u0), h1 = tf32r(u1), h2 = tf32r(u2), h3 = tf32r(u3);
            Ash[r * FA_STRIDE + c] = h0;
            Ash[r * FA_STRIDE + c + 1] = h1;
            Ash[(r + 8) * FA_STRIDE + c] = h2;
            Ash[(r + 8) * FA_STRIDE + c + 1] = h3;
            Asl[r * FA_STRIDE + c] = tf32r(u0 - h0);
            Asl[r * FA_STRIDE + c + 1] = tf32r(u1 - h1);
            Asl[(r + 8) * FA_STRIDE + c] = tf32r(u2 - h2);
            Asl[(r + 8) * FA_STRIDE + c + 1] = tf32r(u3 - h3);
        }
    }
    CP_WAIT(0);
    __syncthreads();

    // ---- stage 2: hB = relu(t @ W2t + b2) ----
#pragma unroll
    for (int mt = 0; mt < 2; mt++)
#pragma unroll
        for (int nt = 0; nt < 4; nt++)
#pragma unroll
            for (int j = 0; j < 4; j++) acc[mt][nt][j] = 0.f;

#pragma unroll 1
    for (int k8 = 0; k8 < 8; k8++) {
        int kb = k8 * 8;
        uint32_t ah[2][4], al[2][4];
#pragma unroll
        for (int mt = 0; mt < 2; mt++) {
            int mr = mrow0 + mt * 16 + gid;
            ah[mt][0] = __float_as_uint(Ash[mr * FA_STRIDE + kb + tig]);
            ah[mt][1] = __float_as_uint(Ash[(mr + 8) * FA_STRIDE + kb + tig]);
            ah[mt][2] = __float_as_uint(Ash[mr * FA_STRIDE + kb + tig + 4]);
            ah[mt][3] = __float_as_uint(Ash[(mr + 8) * FA_STRIDE + kb + tig + 4]);
            al[mt][0] = __float_as_uint(Asl[mr * FA_STRIDE + kb + tig]);
            al[mt][1] = __float_as_uint(Asl[(mr + 8) * FA_STRIDE + kb + tig]);
            al[mt][2] = __float_as_uint(Asl[mr * FA_STRIDE + kb + tig + 4]);
            al[mt][3] = __float_as_uint(Asl[(mr + 8) * FA_STRIDE + kb + tig + 4]);
        }
#pragma unroll
        for (int nt = 0; nt < 4; nt++) {
            int nc = ncol0 + nt * 8 + gid;
            uint32_t bh0 = __float_as_uint(wh[(kb + tig) * FW_STRIDE + nc]);
            uint32_t bh1 = __float_as_uint(wh[(kb + tig + 4) * FW_STRIDE + nc]);
            uint32_t bl0 = __float_as_uint(wl[(kb + tig) * FW_STRIDE + nc]);
            uint32_t bl1 = __float_as_uint(wl[(kb + tig + 4) * FW_STRIDE + nc]);
            mma1688(acc[0][nt], ah[0], bh0, bh1);
            mma1688(acc[0][nt], ah[0], bl0, bl1);
            mma1688(acc[0][nt], al[0], bh0, bh1);
            mma1688(acc[1][nt], ah[1], bh0, bh1);
            mma1688(acc[1][nt], ah[1], bl0, bl1);
            mma1688(acc[1][nt], al[1], bh0, bh1);
        }
    }
    __syncthreads();   // done reading Ash/Asl; free for staging

    // epilogue: outer relu; write global + stage into smem for BN partials
#pragma unroll
    for (int mt = 0; mt < 2; mt++) {
#pragma unroll
        for (int nt = 0; nt < 4; nt++) {
            int r = mrow0 + mt * 16 + gid;
            int c = ncol0 + nt * 8 + tig * 2;
            float bb0 = b2[c], bb1 = b2[c + 1];
            int row = row0 + r;
            float v0 = fmaxf(acc[mt][nt][0] + bb0, 0.f);
            float v1 = fmaxf(acc[mt][nt][1] + bb1, 0.f);
            float v2 = fmaxf(acc[mt][nt][2] + bb0, 0.f);
            float v3 = fmaxf(acc[mt][nt][3] + bb1, 0.f);
            if (row < Nn) {
                *(float2*)&g_hB[(size_t)row * 64 + c] = make_float2(v0, v1);
            } else { v0 = 0.f; v1 = 0.f; }
            if (row + 8 < Nn) {
                *(float2*)&g_hB[(size_t)(row + 8) * 64 + c] = make_float2(v2, v3);
            } else { v2 = 0.f; v3 = 0.f; }
            Ash[r * FA_STRIDE + c] = v0;
            Ash[r * FA_STRIDE + c + 1] = v1;
            Ash[(r + 8) * FA_STRIDE + c] = v2;
            Ash[(r + 8) * FA_STRIDE + c + 1] = v3;
        }
    }
    __syncthreads();

    // deterministic per-CTA BN partials: sum (tid<64) / sumsq (64<=tid<128)
    if (tid < 128) {
        int f = tid & 63;
        bool sq = tid >= 64;
        float s = 0.f;
#pragma unroll 4
        for (int r = 0; r < 128; r++) {
            float v = Ash[r * FA_STRIDE + f];
            s += sq ? v * v : v;
        }
        g_part[blockIdx.x * 128 + tid] = s;
    }
}

// ---------------- BN finalize: reduce 782 per-CTA partials ----------------
__global__ void __launch_bounds__(256)
k_bnfin(const float* __restrict__ gamma, const float* __restrict__ beta) {
    __shared__ float red[256];
    int tid = threadIdx.x;
    int f = tid & 63, g = tid >> 6;
    bool sq = (g >= 2);
    int c0 = (g & 1) ? 391 : 0;
    int c1 = (g & 1) ? NBMMA : 391;
    const float* p = g_part + (sq ? 64 : 0) + f;
    float s = 0.f;
#pragma unroll 4
    for (int c = c0; c < c1; c++) s += p[c * 128];
    red[tid] = s;
    __syncthreads();
    if (tid < 64) {
        float s1 = red[tid] + red[64 + tid];
        float q1 = red[128 + tid] + red[192 + tid];
        float mean = s1 * (1.0f / Nn);
        float var = q1 * (1.0f / Nn) - mean * mean;
        float sc = gamma[tid] * rsqrtf(var + BN_EPS);
        g_scale[tid] = sc;
        g_shift[tid] = fmaf(-mean, sc, beta[tid]);
    }
}

// ---------------- pooling + head ----------------
__global__ void k_bounds(const int* __restrict__ batch) {
    int g = blockIdx.x * blockDim.x + threadIdx.x;
    if (g > Gg) return;
    if (g == Gg) { g_bstart[Gg] = Nn; return; }
    int lo = 0, hi = Nn;
    while (lo < hi) {
        int mid = (lo + hi) >> 1;
        if (batch[mid] < g) lo = mid + 1; else hi = mid;
    }
    g_bstart[g] = lo;
}
__global__ void k_pool() {
    int g = blockIdx.x, d = threadIdx.x;
    int r0 = g_bstart[g], r1 = g_bstart[g + 1];
    float sc = g_scale[d], sh = g_shift[d];
    float s = 0.f;
    for (int r = r0; r < r1; r++) s += fmaf(g_hB[r * 64 + d], sc, sh);
    g_gpool[g * 64 + d] = s;
}
__global__ void k_head(const float* __restrict__ fc1b, const float* __restrict__ fc2b,
                       float* __restrict__ out) {
    __shared__ float gsm[64], tsm[64];
    int g = blockIdx.x, d = threadIdx.x;
    gsm[d] = g_gpool[g * 64 + d];
    __syncthreads();
    float acc = fc1b[d];
    for (int k = 0; k < 64; k++) acc = fmaf(gsm[k], g_fc1Wt[k * 64 + d], acc);
    tsm[d] = fmaxf(acc, 0.f);
    __syncthreads();
    if (d < OUTD) {
        float a2 = fc2b[d];
        for (int k = 0; k < 64; k++) a2 = fmaf(tsm[k], g_fc2Wt[k * 16 + d], a2);
        out[g * OUTD + d] = a2;
    }
}

// ---------------- host ----------------
extern "C" void kernel_launch(void* const* d_in, const int* in_sizes, int n_in,
                              void* d_out, int out_size) {
    const float* x    = (const float*)d_in[0];
    const int*   ei   = (const int*)d_in[1];
    const int*   src  = ei;
    const int*   dst  = ei + Ee;
    const int*   batch = (const int*)d_in[2];
    const float* encW = (const float*)d_in[3];
    const float* encb = (const float*)d_in[4];
    const float* nnW1 = (const float*)d_in[5];
    const float* nnb1 = (const float*)d_in[6];
    const float* nnW2 = (const float*)d_in[7];
    const float* nnb2 = (const float*)d_in[8];
    const float* mlpW = (const float*)d_in[9];
    const float* mlpb = (const float*)d_in[10];
    const float* bnG  = (const float*)d_in[11];
    const float* bnB  = (const float*)d_in[12];
    const float* fc1W = (const float*)d_in[13];
    const float* fc1b = (const float*)d_in[14];
    const float* fc2W = (const float*)d_in[15];
    const float* fc2b = (const float*)d_in[16];
    float* out = (float*)d_out;

    float *p_hB, *p_encWt, *p_fc1Wt, *p_mlpBh, *p_mlpBl;
    float *p_W1h, *p_W1l, *p_W2h, *p_W2l;
    cudaGetSymbolAddress((void**)&p_hB, g_hB);
    cudaGetSymbolAddress((void**)&p_encWt, g_encWt);
    cudaGetSymbolAddress((void**)&p_fc1Wt, g_fc1Wt);
    cudaGetSymbolAddress((void**)&p_mlpBh, g_mlpBh);
    cudaGetSymbolAddress((void**)&p_mlpBl, g_mlpBl);
    cudaGetSymbolAddress((void**)&p_W1h, g_nnW1h);
    cudaGetSymbolAddress((void**)&p_W1l, g_nnW1l);
    cudaGetSymbolAddress((void**)&p_W2h, g_nnW2h);
    cudaGetSymbolAddress((void**)&p_W2l, g_nnW2l);

    cudaFuncSetAttribute(k_pna_mma, cudaFuncAttributeMaxDynamicSharedMemorySize, PNA_SMEM_BYTES);
    cudaFuncSetAttribute(k_nn_mma, cudaFuncAttributeMaxDynamicSharedMemorySize, F_SMEM_BYTES);

    const int NB_SCAN = (Nn + 1023) / 1024;

    // CSR build
    k_zero_deg<<<(Nn + 255) / 256, 256>>>();
    k_count<<<(Ee + 255) / 256, 256>>>(dst);
    k_scan_block<<<NB_SCAN, 1024>>>();
    k_scan_tops<<<1, 1>>>(NB_SCAN);
    k_rowptr<<<(Nn + 255) / 256, 256>>>();
    k_scatter<<<(Ee + 255) / 256, 256>>>(src, dst);
    k_sortrows<<<(Nn + 255) / 256, 256>>>();

    // weight prep (k_tfc2 also sets identity affine for layer 0)
    k_t64<<<(4096 + 255) / 256, 256>>>(encW, p_encWt, 1);
    k_t64<<<(4096 + 255) / 256, 256>>>(fc1W, p_fc1Wt, 1);
    k_t64split<<<(5 * 4096 + 255) / 256, 256>>>(nnW1, p_W1h, p_W1l, 5);
    k_t64split<<<(5 * 4096 + 255) / 256, 256>>>(nnW2, p_W2h, p_W2l, 5);
    k_tmlpB<<<(NL * 256 * 192 + 255) / 256, 256>>>(mlpW);
    k_tfc2<<<(Dd * OUTD + 255) / 256, 256>>>(fc2W);

    const int NBLIN = NnP / 64;

    k_lin64<false><<<NBLIN, 64>>>(x, p_encWt, encb, p_hB);

    for (int i = 0; i < NL; i++) {
        k_agg<<<(Nn * 32 + 255) / 256, 256>>>();
        k_pna_mma<<<NBMMA, 384, PNA_SMEM_BYTES>>>(p_mlpBh + i * 49152, p_mlpBl + i * 49152, mlpb + i * Dd);
        k_nn_mma<<<NBMMA, 256, F_SMEM_BYTES>>>(p_W1h + i * 4096, p_W1l + i * 4096,
                                               p_W2h + i * 4096, p_W2l + i * 4096,
                                               nnb1 + i * Dd, nnb2 + i * Dd);
        k_bnfin<<<1, 256>>>(bnG + i * Dd, bnB + i * Dd);
    }

    k_bounds<<<(Gg + 1 + 255) / 256, 256>>>(batch);
    k_pool<<<Gg, 64>>>();
    k_head<<<Gg, 64>>>(fc1b, fc2b, out);
}

// round 10
// speedup vs baseline: 1.3841x; 1.0727x over previous
#include <cuda_runtime.h>
#include <cfloat>
#include <cstdint>

#define Nn 100000
#define NnP 100096          // multiple of 128 (MMA tile)
#define Ee 1600000
#define Dd 64
#define Gg 512
#define OUTD 16
#define NL 5
#define DELTA 2.5749f
#define BN_EPS 1e-5f
#define NBMMA (NnP / 128)   // 782

// ---------------- static device scratch ----------------
static __device__ float g_hB[NnP * Dd];        // layer output (pre-BN)
static __device__ float g_baseH[NnP * 256];    // [sum|max|mean|var] tf32 hi
static __device__ float g_baseL[NnP * 256];    // tf32 lo residual
static __device__ float g_cfac[NnP];
static __device__ int   g_deg[Nn];
static __device__ int   g_sc[Nn];
static __device__ int   g_bsum[128];
static __device__ int   g_rowptr[Nn + 1];
static __device__ int   g_cursor[Nn];
static __device__ int   g_esrc[Ee];
static __device__ float g_part[NBMMA * 128];   // per-CTA BN partials
static __device__ float g_scale[Dd];
static __device__ float g_shift[Dd];
static __device__ int   g_bstart[Gg + 1];
static __device__ float g_gpool[Gg * Dd];
static __device__ float g_encWt[Dd * Dd];
static __device__ float g_nnW1h[NL * Dd * Dd];  // [k][d] tf32 hi
static __device__ float g_nnW1l[NL * Dd * Dd];
static __device__ float g_nnW2h[NL * Dd * Dd];
static __device__ float g_nnW2l[NL * Dd * Dd];
static __device__ float g_mlpBh[NL * 256 * 192];  // [k][n], tf32 hi
static __device__ float g_mlpBl[NL * 256 * 192];
static __device__ float g_fc1Wt[Dd * Dd];
static __device__ float g_fc2Wt[Dd * OUTD];

__device__ __forceinline__ float tf32r(float x) {
    float y;
    asm("cvt.rna.tf32.f32 %0, %1;" : "=f"(y) : "f"(x));
    return y;
}
__device__ __forceinline__ void mma1688(float* c, const uint32_t* a, uint32_t b0, uint32_t b1) {
    asm volatile(
        "mma.sync.aligned.m16n8k8.row.col.f32.tf32.tf32.f32 "
        "{%0,%1,%2,%3}, {%4,%5,%6,%7}, {%8,%9}, {%0,%1,%2,%3};"
        : "+f"(c[0]), "+f"(c[1]), "+f"(c[2]), "+f"(c[3])
        : "r"(a[0]), "r"(a[1]), "r"(a[2]), "r"(a[3]), "r"(b0), "r"(b1));
}
__device__ __forceinline__ uint32_t smem_u32(const void* p) {
    uint32_t a;
    asm("{ .reg .u64 t; cvta.to.shared.u64 t, %1; cvt.u32.u64 %0, t; }" : "=r"(a) : "l"(p));
    return a;
}
__device__ __forceinline__ void cp16(uint32_t d, const void* s) {
    asm volatile("cp.async.cg.shared.global [%0], [%1], 16;" :: "r"(d), "l"(s));
}
#define CP_COMMIT() asm volatile("cp.async.commit_group;" ::: "memory")
#define CP_WAIT(n)  asm volatile("cp.async.wait_group %0;" :: "n"(n) : "memory")

// ---------------- CSR build ----------------
__global__ void k_zero_deg() {
    int i = blockIdx.x * blockDim.x + threadIdx.x;
    if (i < Nn) g_deg[i] = 0;
}
__global__ void k_count(const int* __restrict__ dst) {
    int e = blockIdx.x * blockDim.x + threadIdx.x;
    if (e < Ee) atomicAdd(&g_deg[dst[e]], 1);
}
__global__ void k_scan_block() {
    __shared__ int sm[1024];
    int i = blockIdx.x * 1024 + threadIdx.x;
    int v = (i < Nn) ? g_deg[i] : 0;
    sm[threadIdx.x] = v;
    __syncthreads();
    for (int off = 1; off < 1024; off <<= 1) {
        int t = 0;
        if (threadIdx.x >= off) t = sm[threadIdx.x - off];
        __syncthreads();
        sm[threadIdx.x] += t;
        __syncthreads();
    }
    if (i < Nn) g_sc[i] = sm[threadIdx.x];
    if (threadIdx.x == 1023) g_bsum[blockIdx.x] = sm[1023];
}
__global__ void k_scan_tops(int nb) {
    if (threadIdx.x == 0 && blockIdx.x == 0) {
        int run = 0;
        for (int b = 0; b < nb; b++) { int t = g_bsum[b]; g_bsum[b] = run; run += t; }
    }
}
__global__ void k_rowptr() {
    int i = blockIdx.x * blockDim.x + threadIdx.x;
    if (i < Nn) {
        int rp = g_sc[i] - g_deg[i] + g_bsum[i >> 10];
        g_rowptr[i] = rp;
        g_cursor[i] = rp;
        g_cfac[i] = fmaxf((float)g_deg[i], 1.0f);
    }
    if (i == 0) g_rowptr[Nn] = Ee;
}
__global__ void k_scatter(const int* __restrict__ src, const int* __restrict__ dst) {
    int e = blockIdx.x * blockDim.x + threadIdx.x;
    if (e < Ee) {
        int p = atomicAdd(&g_cursor[dst[e]], 1);
        g_esrc[p] = src[e];
    }
}
__global__ void k_sortrows() {
    int n = blockIdx.x * blockDim.x + threadIdx.x;
    if (n >= Nn) return;
    int beg = g_rowptr[n], end = g_rowptr[n + 1];
    int deg = end - beg;
    if (deg <= 1) return;
    if (deg <= 64) {
        int buf[64];
        for (int i = 0; i < deg; i++) buf[i] = g_esrc[beg + i];
        for (int i = 1; i < deg; i++) {
            int v = buf[i];
            int j = i - 1;
            while (j >= 0 && buf[j] > v) { buf[j + 1] = buf[j]; j--; }
            buf[j + 1] = v;
        }
        for (int i = 0; i < deg; i++) g_esrc[beg + i] = buf[i];
    } else {
        for (int i = beg + 1; i < end; i++) {
            int v = g_esrc[i];
            int j = i - 1;
            while (j >= beg && g_esrc[j] > v) { g_esrc[j + 1] = g_esrc[j]; j--; }
            g_esrc[j + 1] = v;
        }
    }
}

// ---------------- weight prep ----------------
__global__ void k_t64(const float* __restrict__ W, float* __restrict__ Wt, int nm) {
    int idx = blockIdx.x * blockDim.x + threadIdx.x;
    if (idx >= nm * 4096) return;
    int m = idx >> 12, r = idx & 4095;
    int d = r >> 6, k = r & 63;
    Wt[(m << 12) + (k << 6) + d] = W[idx];
}
__global__ void k_t64split(const float* __restrict__ W, float* __restrict__ Wh,
                           float* __restrict__ Wl, int nm) {
    int idx = blockIdx.x * blockDim.x + threadIdx.x;
    if (idx >= nm * 4096) return;
    int m = idx >> 12, r = idx & 4095;
    int d = r >> 6, k = r & 63;
    float w = W[idx];
    float h = tf32r(w);
    Wh[(m << 12) + (k << 6) + d] = h;
    Wl[(m << 12) + (k << 6) + d] = tf32r(w - h);
}
__global__ void k_tmlpB(const float* __restrict__ W) {
    int idx = blockIdx.x * blockDim.x + threadIdx.x;
    if (idx >= NL * 256 * 192) return;
    int m = idx / 49152, r = idx % 49152;
    int k = r / 192, n = r % 192;
    int d = n & 63, b = n >> 6;
    float w = W[m * 49152 + d * 768 + b * 256 + k];
    float h = tf32r(w);
    g_mlpBh[idx] = h;
    g_mlpBl[idx] = tf32r(w - h);
}
// also initializes identity affine for layer 0
__global__ void k_tfc2(const float* __restrict__ W) {
    int idx = blockIdx.x * blockDim.x + threadIdx.x;
    if (idx < 64) { g_scale[idx] = 1.0f; g_shift[idx] = 0.0f; }
    if (idx >= Dd * OUTD) return;
    int o = idx >> 6, k = idx & 63;
    g_fc2Wt[k * 16 + o] = W[idx];
}

// ---------------- 64x64 linear (encoder only) ----------------
template <bool RELU>
__global__ void __launch_bounds__(64) k_lin64(const float* __restrict__ A,
                                              const float* __restrict__ Wt,
                                              const float* __restrict__ b,
                                              float* __restrict__ C) {
    __shared__ float4 Asm[64][16];
    int row0 = blockIdx.x * 64, tid = threadIdx.x;
    for (int t = tid; t < 1024; t += 64) {
        int r = t >> 4, c = t & 15;
        float4 v = make_float4(0.f, 0.f, 0.f, 0.f);
        if (row0 + r < Nn) v = ((const float4*)A)[(row0 + r) * 16 + c];
        Asm[r][c] = v;
    }
    __syncthreads();
    float acc[64];
#pragma unroll
    for (int r = 0; r < 64; r++) acc[r] = 0.f;
#pragma unroll 1
    for (int k4 = 0; k4 < 16; k4++) {
        float w0 = Wt[(k4 * 4 + 0) * 64 + tid];
        float w1 = Wt[(k4 * 4 + 1) * 64 + tid];
        float w2 = Wt[(k4 * 4 + 2) * 64 + tid];
        float w3 = Wt[(k4 * 4 + 3) * 64 + tid];
#pragma unroll
        for (int r = 0; r < 64; r++) {
            float4 a = Asm[r][k4];
            float t0 = fmaf(a.x, w0, acc[r]);
            t0 = fmaf(a.y, w1, t0);
            t0 = fmaf(a.z, w2, t0);
            acc[r] = fmaf(a.w, w3, t0);
        }
    }
    float bb = b[tid];
    for (int r = 0; r < 64; r++) {
        if (row0 + r < Nn) {
            float v = acc[r] + bb;
            if (RELU) v = fmaxf(v, 0.f);
            C[(row0 + r) * 64 + tid] = v;
        }
    }
}

// ---------------- PNA aggregation (warp/node, affine on the fly, 4-way unroll) ----------------
__global__ void k_agg() {
    int gt = blockIdx.x * blockDim.x + threadIdx.x;
    int w = gt >> 5, lane = gt & 31;
    if (w >= Nn) return;
    int beg = g_rowptr[w], end = g_rowptr[w + 1];
    const float2* hp = (const float2*)g_hB;
    float scx = g_scale[2 * lane], scy = g_scale[2 * lane + 1];
    float shx = g_shift[2 * lane], shy = g_shift[2 * lane + 1];
    float sxA = 0.f, syA = 0.f, qxA = 0.f, qyA = 0.f;
    float sxB = 0.f, syB = 0.f, qxB = 0.f, qyB = 0.f;
    float mxx = -FLT_MAX, mxy = -FLT_MAX;
    int j = beg;
    for (; j + 3 < end; j += 4) {
        int s0 = g_esrc[j];
        int s1 = g_esrc[j + 1];
        int s2 = g_esrc[j + 2];
        int s3 = g_esrc[j + 3];
        float2 r0 = hp[s0 * 32 + lane];
        float2 r1 = hp[s1 * 32 + lane];
        float2 r2 = hp[s2 * 32 + lane];
        float2 r3 = hp[s3 * 32 + lane];
        float v0x = fmaf(r0.x, scx, shx), v0y = fmaf(r0.y, scy, shy);
        float v1x = fmaf(r1.x, scx, shx), v1y = fmaf(r1.y, scy, shy);
        float v2x = fmaf(r2.x, scx, shx), v2y = fmaf(r2.y, scy, shy);
        float v3x = fmaf(r3.x, scx, shx), v3y = fmaf(r3.y, scy, shy);
        sxA += v0x; syA += v0y;
        qxA = fmaf(v0x, v0x, qxA); qyA = fmaf(v0y, v0y, qyA);
        mxx = fmaxf(mxx, v0x); mxy = fmaxf(mxy, v0y);
        sxB += v1x; syB += v1y;
        qxB = fmaf(v1x, v1x, qxB); qyB = fmaf(v1y, v1y, qyB);
        mxx = fmaxf(mxx, v1x); mxy = fmaxf(mxy, v1y);
        sxA += v2x; syA += v2y;
        qxA = fmaf(v2x, v2x, qxA); qyA = fmaf(v2y, v2y, qyA);
        mxx = fmaxf(mxx, v2x); mxy = fmaxf(mxy, v2y);
        sxB += v3x; syB += v3y;
        qxB = fmaf(v3x, v3x, qxB); qyB = fmaf(v3y, v3y, qyB);
        mxx = fmaxf(mxx, v3x); mxy = fmaxf(mxy, v3y);
    }
    for (; j < end; j++) {
        int s0 = g_esrc[j];
        float2 r0 = hp[s0 * 32 + lane];
        float v0x = fmaf(r0.x, scx, shx), v0y = fmaf(r0.y, scy, shy);
        sxA += v0x; syA += v0y;
        qxA = fmaf(v0x, v0x, qxA); qyA = fmaf(v0y, v0y, qyA);
        mxx = fmaxf(mxx, v0x); mxy = fmaxf(mxy, v0y);
    }
    float sx = sxA + sxB, sy = syA + syB;
    float qx = qxA + qxB, qy = qyA + qyB;
    if (end == beg) { mxx = 0.f; mxy = 0.f; }
    float c = g_cfac[w];
    float inv = 1.f / c;
    float mex = sx * inv, mey = sy * inv;
    float vx = fmaxf(qx * inv - mex * mex, 0.f);
    float vy = fmaxf(qy * inv - mey * mey, 0.f);
    float2* bpH = (float2*)(g_baseH + (size_t)w * 256);
    float2* bpL = (float2*)(g_baseL + (size_t)w * 256);
    float hx, hy;
    hx = tf32r(sx);  hy = tf32r(sy);
    bpH[lane]      = make_float2(hx, hy);
    bpL[lane]      = make_float2(tf32r(sx - hx), tf32r(sy - hy));
    hx = tf32r(mxx); hy = tf32r(mxy);
    bpH[32 + lane] = make_float2(hx, hy);
    bpL[32 + lane] = make_float2(tf32r(mxx - hx), tf32r(mxy - hy));
    hx = tf32r(mex); hy = tf32r(mey);
    bpH[64 + lane] = make_float2(hx, hy);
    bpL[64 + lane] = make_float2(tf32r(mex - hx), tf32r(mey - hy));
    hx = tf32r(vx);  hy = tf32r(vy);
    bpH[96 + lane] = make_float2(hx, hy);
    bpL[96 + lane] = make_float2(tf32r(vx - hx), tf32r(vy - hy));
}

// ---------------- merged layer kernel ----------------
// phase 1: pipelined 3xTF32 GEMM S = base @ B  (12 warps, 4m x 3n)
// phase 2: stage S + prefetch W1; combine -> nn A fragments (smem)
// phase 3: nn stage1/stage2 (warps 0-7, 4m x 2n), W2 prefetched under resplit
// phase 4: epilogue writes g_hB + deterministic BN partials
#define AS_STRIDE 36
#define BS_STRIDE 200
#define SS_STRIDE 200
#define P_AH 0
#define P_AL 4608
#define P_BH 9216
#define P_BL 15616
#define PSTG 22016
#define FA_STRIDE 68
#define FW_STRIDE 72
#define L_ASH 25600
#define L_ASL (L_ASH + 128 * FA_STRIDE)   // 34304
#define L_WH  (L_ASL + 128 * FA_STRIDE)   // 43008
#define L_WL  (L_WH + 64 * FW_STRIDE)     // 47616
#define L_SMEM_FLOATS (L_WL + 64 * FW_STRIDE)  // 52224
#define L_SMEM_BYTES (L_SMEM_FLOATS * 4)       // 208896

__global__ void __launch_bounds__(384)
k_layer(const float* __restrict__ Bh, const float* __restrict__ Bl,
        const float* __restrict__ mb,
        const float* __restrict__ W1h, const float* __restrict__ W1l,
        const float* __restrict__ W2h, const float* __restrict__ W2l,
        const float* __restrict__ b1, const float* __restrict__ b2) {
    extern __shared__ float sm[];
    uint32_t sb = smem_u32(sm);
    int tid = threadIdx.x, wid = tid >> 5, lane = tid & 31;
    int gid = lane >> 2, tig = lane & 3;
    int row0 = blockIdx.x * 128;
    int mrow0 = (wid & 3) * 32;
    int ncol0p = (wid >> 2) * 64;   // pna n offset
    int ncol0f = (wid >> 2) * 32;   // nn n offset (warps 0-7)

    // ---- phase 1: pna GEMM mainloop (double-buffered cp.async) ----
    auto load_stage = [&](int kc, int buf) {
        uint32_t aH = sb + (uint32_t)(buf * PSTG + P_AH) * 4;
        uint32_t aL = sb + (uint32_t)(buf * PSTG + P_AL) * 4;
        uint32_t bH = sb + (uint32_t)(buf * PSTG + P_BH) * 4;
        uint32_t bL = sb + (uint32_t)(buf * PSTG + P_BL) * 4;
        for (int i = tid; i < 1024; i += 384) {
            int r = i >> 3, c4 = i & 7;
            uint32_t off = (uint32_t)(r * AS_STRIDE + c4 * 4) * 4;
            size_t go = (size_t)(row0 + r) * 256 + kc * 32 + c4 * 4;
            cp16(aH + off, &g_baseH[go]);
            cp16(aL + off, &g_baseL[go]);
        }
        for (int i = tid; i < 1536; i += 384) {
            int r = i / 48, c4 = i % 48;
            uint32_t off = (uint32_t)(r * BS_STRIDE + c4 * 4) * 4;
            size_t go = (size_t)(kc * 32 + r) * 192 + c4 * 4;
            cp16(bH + off, &Bh[go]);
            cp16(bL + off, &Bl[go]);
        }
    };

    float acc[2][8][4];
#pragma unroll
    for (int mt = 0; mt < 2; mt++)
#pragma unroll
        for (int nt = 0; nt < 8; nt++)
#pragma unroll
            for (int j = 0; j < 4; j++) acc[mt][nt][j] = 0.f;

    load_stage(0, 0);
    CP_COMMIT();

#pragma unroll 1
    for (int kc = 0; kc < 8; kc++) {
        if (kc < 7) {
            load_stage(kc + 1, (kc + 1) & 1);
            CP_COMMIT();
            CP_WAIT(1);
        } else {
            CP_WAIT(0);
        }
        __syncthreads();
        const float* Ash = sm + (kc & 1) * PSTG + P_AH;
        const float* Asl = sm + (kc & 1) * PSTG + P_AL;
        const float* Bsh = sm + (kc & 1) * PSTG + P_BH;
        const float* Bsl = sm + (kc & 1) * PSTG + P_BL;
#pragma unroll
        for (int k8 = 0; k8 < 4; k8++) {
            int kb = k8 * 8;
            uint32_t ah[2][4], al[2][4];
#pragma unroll
            for (int mt = 0; mt < 2; mt++) {
                int mr = mrow0 + mt * 16 + gid;
                ah[mt][0] = __float_as_uint(Ash[mr * AS_STRIDE + kb + tig]);
                ah[mt][1] = __float_as_uint(Ash[(mr + 8) * AS_STRIDE + kb + tig]);
                ah[mt][2] = __float_as_uint(Ash[mr * AS_STRIDE + kb + tig + 4]);
                ah[mt][3] = __float_as_uint(Ash[(mr + 8) * AS_STRIDE + kb + tig + 4]);
                al[mt][0] = __float_as_uint(Asl[mr * AS_STRIDE + kb + tig]);
                al[mt][1] = __float_as_uint(Asl[(mr + 8) * AS_STRIDE + kb + tig]);
                al[mt][2] = __float_as_uint(Asl[mr * AS_STRIDE + kb + tig + 4]);
                al[mt][3] = __float_as_uint(Asl[(mr + 8) * AS_STRIDE + kb + tig + 4]);
            }
#pragma unroll
            for (int nt = 0; nt < 8; nt++) {
                int nc = ncol0p + nt * 8 + gid;
                uint32_t bh0 = __float_as_uint(Bsh[(kb + tig) * BS_STRIDE + nc]);
                uint32_t bh1 = __float_as_uint(Bsh[(kb + tig + 4) * BS_STRIDE + nc]);
                uint32_t bl0 = __float_as_uint(Bsl[(kb + tig) * BS_STRIDE + nc]);
                uint32_t bl1 = __float_as_uint(Bsl[(kb + tig + 4) * BS_STRIDE + nc]);
                mma1688(acc[0][nt], ah[0], bh0, bh1);
                mma1688(acc[0][nt], ah[0], bl0, bl1);
                mma1688(acc[0][nt], al[0], bh0, bh1);
                mma1688(acc[1][nt], ah[1], bh0, bh1);
                mma1688(acc[1][nt], ah[1], bl0, bl1);
                mma1688(acc[1][nt], al[1], bh0, bh1);
            }
        }
        __syncthreads();
    }

    // ---- phase 2: prefetch W1, stage S, combine -> nn fragments ----
    {
        uint32_t whA = sb + L_WH * 4, wlA = sb + L_WL * 4;
        for (int i = tid; i < 2048; i += 384) {
            int c = i & 1023;
            int k = c >> 4, c4 = c & 15;
            uint32_t off = (uint32_t)(k * FW_STRIDE + c4 * 4) * 4;
            if (i < 1024) cp16(whA + off, &W1h[c * 4]);
            else          cp16(wlA + off, &W1l[c * 4]);
        }
        CP_COMMIT();
    }
#pragma unroll
    for (int mt = 0; mt < 2; mt++) {
#pragma unroll
        for (int nt = 0; nt < 8; nt++) {
            int r = mrow0 + mt * 16 + gid;
            int c = ncol0p + nt * 8 + tig * 2;
            *(float2*)&sm[r * SS_STRIDE + c] = make_float2(acc[mt][nt][0], acc[mt][nt][1]);
            *(float2*)&sm[(r + 8) * SS_STRIDE + c] = make_float2(acc[mt][nt][2], acc[mt][nt][3]);
        }
    }
    __syncthreads();

    // combine: u = affine(hB) + mb + S0 + (c/D)S1 + (D/c)S2 -> split into Ash/Asl
    {
        float* Af = sm + L_ASH;
        float* Al = sm + L_ASL;
        for (int i = tid; i < 128 * 64; i += 384) {
            int r = i >> 6, d = i & 63;
            int row = row0 + r;
            float h = 0.f, l = 0.f;
            if (row < Nn) {
                float cf = g_cfac[row];
                float aa = cf * (1.0f / DELTA);
                float b2c = DELTA / cf;
                const float* Sr = sm + r * SS_STRIDE;
                float x = fmaf(g_hB[(size_t)row * 64 + d], g_scale[d], g_shift[d]);
                float v = x + mb[d] + Sr[d] + aa * Sr[64 + d] + b2c * Sr[128 + d];
                h = tf32r(v);
                l = tf32r(v - h);
            }
            Af[r * FA_STRIDE + d] = h;
            Al[r * FA_STRIDE + d] = l;
        }
    }
    CP_WAIT(0);
    __syncthreads();

    // ---- phase 3: nn stage 1 (warps 0-7) ----
    float acc2[2][4][4];
    const float* Af = sm + L_ASH;
    const float* Al = sm + L_ASL;
    const float* wh = sm + L_WH;
    const float* wl = sm + L_WL;
    if (wid < 8) {
#pragma unroll
        for (int mt = 0; mt < 2; mt++)
#pragma unroll
            for (int nt = 0; nt < 4; nt++)
#pragma unroll
                for (int j = 0; j < 4; j++) acc2[mt][nt][j] = 0.f;
#pragma unroll 1
        for (int k8 = 0; k8 < 8; k8++) {
            int kb = k8 * 8;
            uint32_t ah[2][4], al2[2][4];
#pragma unroll
            for (int mt = 0; mt < 2; mt++) {
                int mr = mrow0 + mt * 16 + gid;
                ah[mt][0] = __float_as_uint(Af[mr * FA_STRIDE + kb + tig]);
                ah[mt][1] = __float_as_uint(Af[(mr + 8) * FA_STRIDE + kb + tig]);
                ah[mt][2] = __float_as_uint(Af[mr * FA_STRIDE + kb + tig + 4]);
                ah[mt][3] = __float_as_uint(Af[(mr + 8) * FA_STRIDE + kb + tig + 4]);
                al2[mt][0] = __float_as_uint(Al[mr * FA_STRIDE + kb + tig]);
                al2[mt][1] = __float_as_uint(Al[(mr + 8) * FA_STRIDE + kb + tig]);
                al2[mt][2] = __float_as_uint(Al[mr * FA_STRIDE + kb + tig + 4]);
                al2[mt][3] = __float_as_uint(Al[(mr + 8) * FA_STRIDE + kb + tig + 4]);
            }
#pragma unroll
            for (int nt = 0; nt < 4; nt++) {
                int nc = ncol0f + nt * 8 + gid;
                uint32_t bh0 = __float_as_uint(wh[(kb + tig) * FW_STRIDE + nc]);
                uint32_t bh1 = __float_as_uint(wh[(kb + tig + 4) * FW_STRIDE + nc]);
                uint32_t bl0 = __float_as_uint(wl[(kb + tig) * FW_STRIDE + nc]);
                uint32_t bl1 = __float_as_uint(wl[(kb + tig + 4) * FW_STRIDE + nc]);
                mma1688(acc2[0][nt], ah[0], bh0, bh1);
                mma1688(acc2[0][nt], ah[0], bl0, bl1);
                mma1688(acc2[0][nt], al2[0], bh0, bh1);
                mma1688(acc2[1][nt], ah[1], bh0, bh1);
                mma1688(acc2[1][nt], ah[1], bl0, bl1);
                mma1688(acc2[1][nt], al2[1], bh0, bh1);
            }
        }
    }
    __syncthreads();   // all reads of W1 + A fragments done

    // async load W2 into same weight buffer; hide under relu-resplit
    {
        uint32_t whA = sb + L_WH * 4, wlA = sb + L_WL * 4;
        for (int i = tid; i < 2048; i += 384) {
            int c = i & 1023;
            int k = c >> 4, c4 = c & 15;
            uint32_t off = (uint32_t)(k * FW_STRIDE + c4 * 4) * 4;
            if (i < 1024) cp16(whA + off, &W2h[c * 4]);
            else          cp16(wlA + off, &W2l[c * 4]);
        }
        CP_COMMIT();
    }
    // relu + bias, re-split into A fragments
    if (wid < 8) {
        float* Afw = sm + L_ASH;
        float* Alw = sm + L_ASL;
#pragma unroll
        for (int mt = 0; mt < 2; mt++) {
#pragma unroll
            for (int nt = 0; nt < 4; nt++) {
                int r = mrow0 + mt * 16 + gid;
                int c = ncol0f + nt * 8 + tig * 2;
                float bb0 = b1[c], bb1 = b1[c + 1];
                float u0 = fmaxf(acc2[mt][nt][0] + bb0, 0.f);
                float u1 = fmaxf(acc2[mt][nt][1] + bb1, 0.f);
                float u2 = fmaxf(acc2[mt][nt][2] + bb0, 0.f);
                float u3 = fmaxf(acc2[mt][nt][3] + bb1, 0.f);
                float h0 = tf32r(u0), h1 = tf32r(u1), h2 = tf32r(u2), h3 = tf32r(u3);
                Afw[r * FA_STRIDE + c] = h0;
                Afw[r * FA_STRIDE + c + 1] = h1;
                Afw[(r + 8) * FA_STRIDE + c] = h2;
                Afw[(r + 8) * FA_STRIDE + c + 1] = h3;
                Alw[r * FA_STRIDE + c] = tf32r(u0 - h0);
                Alw[r * FA_STRIDE + c + 1] = tf32r(u1 - h1);
                Alw[(r + 8) * FA_STRIDE + c] = tf32r(u2 - h2);
                Alw[(r + 8) * FA_STRIDE + c + 1] = tf32r(u3 - h3);
            }
        }
    }
    CP_WAIT(0);
    __syncthreads();

    // ---- nn stage 2 ----
    if (wid < 8) {
#pragma unroll
        for (int mt = 0; mt < 2; mt++)
#pragma unroll
            for (int nt = 0; nt < 4; nt++)
#pragma unroll
                for (int j = 0; j < 4; j++) acc2[mt][nt][j] = 0.f;
#pragma unroll 1
        for (int k8 = 0; k8 < 8; k8++) {
            int kb = k8 * 8;
            uint32_t ah[2][4], al2[2][4];
#pragma unroll
            for (int mt = 0; mt < 2; mt++) {
                int mr = mrow0 + mt * 16 + gid;
                ah[mt][0] = __float_as_uint(Af[mr * FA_STRIDE + kb + tig]);
                ah[mt][1] = __float_as_uint(Af[(mr + 8) * FA_STRIDE + kb + tig]);
                ah[mt][2] = __float_as_uint(Af[mr * FA_STRIDE + kb + tig + 4]);
                ah[mt][3] = __float_as_uint(Af[(mr + 8) * FA_STRIDE + kb + tig + 4]);
                al2[mt][0] = __float_as_uint(Al[mr * FA_STRIDE + kb + tig]);
                al2[mt][1] = __float_as_uint(Al[(mr + 8) * FA_STRIDE + kb + tig]);
                al2[mt][2] = __float_as_uint(Al[mr * FA_STRIDE + kb + tig + 4]);
                al2[mt][3] = __float_as_uint(Al[(mr + 8) * FA_STRIDE + kb + tig + 4]);
            }
#pragma unroll
            for (int nt = 0; nt < 4; nt++) {
                int nc = ncol0f + nt * 8 + gid;
                uint32_t bh0 = __float_as_uint(wh[(kb + tig) * FW_STRIDE + nc]);
                uint32_t bh1 = __float_as_uint(wh[(kb + tig + 4) * FW_STRIDE + nc]);
                uint32_t bl0 = __float_as_uint(wl[(kb + tig) * FW_STRIDE + nc]);
                uint32_t bl1 = __float_as_uint(wl[(kb + tig + 4) * FW_STRIDE + nc]);
                mma1688(acc2[0][nt], ah[0], bh0, bh1);
                mma1688(acc2[0][nt], ah[0], bl0, bl1);
                mma1688(acc2[0][nt], al2[0], bh0, bh1);
                mma1688(acc2[1][nt], ah[1], bh0, bh1);
                mma1688(acc2[1][nt], ah[1], bl0, bl1);
                mma1688(acc2[1][nt], al2[1], bh0, bh1);
            }
        }
    }
    __syncthreads();   // A fragments free for output staging

    // ---- phase 4: epilogue (outer relu) + BN staging ----
    if (wid < 8) {
        float* Afw = sm + L_ASH;
#pragma unroll
        for (int mt = 0; mt < 2; mt++) {
#pragma unroll
            for (int nt = 0; nt < 4; nt++) {
                int r = mrow0 + mt * 16 + gid;
                int c = ncol0f + nt * 8 + tig * 2;
                float bb0 = b2[c], bb1 = b2[c + 1];
                int row = row0 + r;
                float v0 = fmaxf(acc2[mt][nt][0] + bb0, 0.f);
                float v1 = fmaxf(acc2[mt][nt][1] + bb1, 0.f);
                float v2 = fmaxf(acc2[mt][nt][2] + bb0, 0.f);
                float v3 = fmaxf(acc2[mt][nt][3] + bb1, 0.f);
                if (row < Nn) {
                    *(float2*)&g_hB[(size_t)row * 64 + c] = make_float2(v0, v1);
                } else { v0 = 0.f; v1 = 0.f; }
                if (row + 8 < Nn) {
                    *(float2*)&g_hB[(size_t)(row + 8) * 64 + c] = make_float2(v2, v3);
                } else { v2 = 0.f; v3 = 0.f; }
                Afw[r * FA_STRIDE + c] = v0;
                Afw[r * FA_STRIDE + c + 1] = v1;
                Afw[(r + 8) * FA_STRIDE + c] = v2;
                Afw[(r + 8) * FA_STRIDE + c + 1] = v3;
            }
        }
    }
    __syncthreads();

    if (tid < 128) {
        int f = tid & 63;
        bool sq = tid >= 64;
        const float* Afr = sm + L_ASH;
        float s = 0.f;
#pragma unroll 4
        for (int r = 0; r < 128; r++) {
            float v = Afr[r * FA_STRIDE + f];
            s += sq ? v * v : v;
        }
        g_part[blockIdx.x * 128 + tid] = s;
    }
}

// ---------------- BN finalize: grid=64 (one CTA per feature) ----------------
__global__ void __launch_bounds__(256)
k_bnfin(const float* __restrict__ gamma, const float* __restrict__ beta) {
    __shared__ float red[512];
    int f = blockIdx.x, tid = threadIdx.x;
    float s = 0.f, q = 0.f;
    for (int c = tid; c < NBMMA; c += 256) {
        s += g_part[c * 128 + f];
        q += g_part[c * 128 + 64 + f];
    }
    red[tid] = s;
    red[256 + tid] = q;
    __syncthreads();
    for (int off = 128; off > 0; off >>= 1) {
        if (tid < off) {
            red[tid] += red[tid + off];
            red[256 + tid] += red[256 + tid + off];
        }
        __syncthreads();
    }
    if (tid == 0) {
        float mean = red[0] * (1.0f / Nn);
        float var = red[256] * (1.0f / Nn) - mean * mean;
        float sc = gamma[f] * rsqrtf(var + BN_EPS);
        g_scale[f] = sc;
        g_shift[f] = fmaf(-mean, sc, beta[f]);
    }
}

// ---------------- pooling + head ----------------
__global__ void k_bounds(const int* __restrict__ batch) {
    int g = blockIdx.x * blockDim.x + threadIdx.x;
    if (g > Gg) return;
    if (g == Gg) { g_bstart[Gg] = Nn; return; }
    int lo = 0, hi = Nn;
    while (lo < hi) {
        int mid = (lo + hi) >> 1;
        if (batch[mid] < g) lo = mid + 1; else hi = mid;
    }
    g_bstart[g] = lo;
}
__global__ void k_pool() {
    int g = blockIdx.x, d = threadIdx.x;
    int r0 = g_bstart[g], r1 = g_bstart[g + 1];
    float sc = g_scale[d], sh = g_shift[d];
    float s = 0.f;
    for (int r = r0; r < r1; r++) s += fmaf(g_hB[r * 64 + d], sc, sh);
    g_gpool[g * 64 + d] = s;
}
__global__ void k_head(const float* __restrict__ fc1b, const float* __restrict__ fc2b,
                       float* __restrict__ out) {
    __shared__ float gsm[64], tsm[64];
    int g = blockIdx.x, d = threadIdx.x;
    gsm[d] = g_gpool[g * 64 + d];
    __syncthreads();
    float acc = fc1b[d];
    for (int k = 0; k < 64; k++) acc = fmaf(gsm[k], g_fc1Wt[k * 64 + d], acc);
    tsm[d] = fmaxf(acc, 0.f);
    __syncthreads();
    if (d < OUTD) {
        float a2 = fc2b[d];
        for (int k = 0; k < 64; k++) a2 = fmaf(tsm[k], g_fc2Wt[k * 16 + d], a2);
        out[g * OUTD + d] = a2;
    }
}

// ---------------- host ----------------
extern "C" void kernel_launch(void* const* d_in, const int* in_sizes, int n_in,
                              void* d_out, int out_size) {
    const float* x    = (const float*)d_in[0];
    const int*   ei   = (const int*)d_in[1];
    const int*   src  = ei;
    const int*   dst  = ei + Ee;
    const int*   batch = (const int*)d_in[2];
    const float* encW = (const float*)d_in[3];
    const float* encb = (const float*)d_in[4];
    const float* nnW1 = (const float*)d_in[5];
    const float* nnb1 = (const float*)d_in[6];
    const float* nnW2 = (const float*)d_in[7];
    const float* nnb2 = (const float*)d_in[8];
    const float* mlpW = (const float*)d_in[9];
    const float* mlpb = (const float*)d_in[10];
    const float* bnG  = (const float*)d_in[11];
    const float* bnB  = (const float*)d_in[12];
    const float* fc1W = (const float*)d_in[13];
    const float* fc1b = (const float*)d_in[14];
    const float* fc2W = (const float*)d_in[15];
    const float* fc2b = (const float*)d_in[16];
    float* out = (float*)d_out;

    float *p_hB, *p_encWt, *p_fc1Wt, *p_mlpBh, *p_mlpBl;
    float *p_W1h, *p_W1l, *p_W2h, *p_W2l;
    cudaGetSymbolAddress((void**)&p_hB, g_hB);
    cudaGetSymbolAddress((void**)&p_encWt, g_encWt);
    cudaGetSymbolAddress((void**)&p_fc1Wt, g_fc1Wt);
    cudaGetSymbolAddress((void**)&p_mlpBh, g_mlpBh);
    cudaGetSymbolAddress((void**)&p_mlpBl, g_mlpBl);
    cudaGetSymbolAddress((void**)&p_W1h, g_nnW1h);
    cudaGetSymbolAddress((void**)&p_W1l, g_nnW1l);
    cudaGetSymbolAddress((void**)&p_W2h, g_nnW2h);
    cudaGetSymbolAddress((void**)&p_W2l, g_nnW2l);

    cudaFuncSetAttribute(k_layer, cudaFuncAttributeMaxDynamicSharedMemorySize, L_SMEM_BYTES);

    const int NB_SCAN = (Nn + 1023) / 1024;

    // CSR build
    k_zero_deg<<<(Nn + 255) / 256, 256>>>();
    k_count<<<(Ee + 255) / 256, 256>>>(dst);
    k_scan_block<<<NB_SCAN, 1024>>>();
    k_scan_tops<<<1, 1>>>(NB_SCAN);
    k_rowptr<<<(Nn + 255) / 256, 256>>>();
    k_scatter<<<(Ee + 255) / 256, 256>>>(src, dst);
    k_sortrows<<<(Nn + 255) / 256, 256>>>();

    // weight prep (k_tfc2 also sets identity affine for layer 0)
    k_t64<<<(4096 + 255) / 256, 256>>>(encW, p_encWt, 1);
    k_t64<<<(4096 + 255) / 256, 256>>>(fc1W, p_fc1Wt, 1);
    k_t64split<<<(5 * 4096 + 255) / 256, 256>>>(nnW1, p_W1h, p_W1l, 5);
    k_t64split<<<(5 * 4096 + 255) / 256, 256>>>(nnW2, p_W2h, p_W2l, 5);
    k_tmlpB<<<(NL * 256 * 192 + 255) / 256, 256>>>(mlpW);
    k_tfc2<<<(Dd * OUTD + 255) / 256, 256>>>(fc2W);

    const int NBLIN = NnP / 64;

    k_lin64<false><<<NBLIN, 64>>>(x, p_encWt, encb, p_hB);

    for (int i = 0; i < NL; i++) {
        k_agg<<<(Nn * 32 + 255) / 256, 256>>>();
        k_layer<<<NBMMA, 384, L_SMEM_BYTES>>>(p_mlpBh + i * 49152, p_mlpBl + i * 49152,
                                              mlpb + i * Dd,
                                              p_W1h + i * 4096, p_W1l + i * 4096,
                                              p_W2h + i * 4096, p_W2l + i * 4096,
                                              nnb1 + i * Dd, nnb2 + i * Dd);
        k_bnfin<<<64, 256>>>(bnG + i * Dd, bnB + i * Dd);
    }

    k_bounds<<<(Gg + 1 + 255) / 256, 256>>>(batch);
    k_pool<<<Gg, 64>>>();
    k_head<<<Gg, 64>>>(fc1b, fc2b, out);
}